// round 4
// baseline (speedup 1.0000x reference)
#include <cuda_runtime.h>
#include <math.h>

#define NODES_MAX 50000
#define HID 256
#define OUTC 64
#define INC 512
#define EDGES_MAX 800000

// ---------------- scratch (static __device__ per allocation rules) ----------
__device__ float g_h1[(size_t)NODES_MAX * HID];     // x @ W1
__device__ float g_agg1[(size_t)NODES_MAX * HID];   // relu(norm-agg(h1) + b1)
__device__ float g_h2[(size_t)NODES_MAX * OUTC];    // agg1 @ W2
__device__ float g_dinv[NODES_MAX];
__device__ int   g_cnt[NODES_MAX];
__device__ int   g_indptr[NODES_MAX + 1];
__device__ int   g_cursor[NODES_MAX];
__device__ int   g_srcs[EDGES_MAX];

// ---------------- graph preprocessing ---------------------------------------
__global__ void k_zero_cnt(int n) {
    int i = blockIdx.x * blockDim.x + threadIdx.x;
    if (i < n) g_cnt[i] = 0;
}

// edge_index is INT32 (JAX x64 disabled downcasts jnp.int64 -> int32).
__global__ void k_count(const int* __restrict__ dst, int E, int n) {
    int i = blockIdx.x * blockDim.x + threadIdx.x;
    if (i < E) {
        int d = dst[i];
        d = max(0, min(n - 1, d));          // clamp: trap-proof
        atomicAdd(&g_cnt[d], 1);
    }
}

__global__ void k_dinv(int n) {
    int i = blockIdx.x * blockDim.x + threadIdx.x;
    if (i < n) g_dinv[i] = rsqrtf((float)(g_cnt[i] + 1));  // +1 self loop
}

// single-block exclusive scan of g_cnt -> g_indptr / g_cursor
__global__ void k_scan(int n) {
    __shared__ int sh[1024];
    __shared__ int carry;
    if (threadIdx.x == 0) carry = 0;
    __syncthreads();
    for (int base = 0; base < n; base += 1024) {
        int i = base + threadIdx.x;
        int v = (i < n) ? g_cnt[i] : 0;
        sh[threadIdx.x] = v;
        __syncthreads();
        #pragma unroll
        for (int off = 1; off < 1024; off <<= 1) {
            int t = (threadIdx.x >= off) ? sh[threadIdx.x - off] : 0;
            __syncthreads();
            sh[threadIdx.x] += t;
            __syncthreads();
        }
        int excl = sh[threadIdx.x] - v;
        if (i < n) {
            int p = carry + excl;
            g_indptr[i] = p;
            g_cursor[i] = p;
        }
        __syncthreads();
        if (threadIdx.x == 1023) carry += sh[1023];
        __syncthreads();
    }
    if (threadIdx.x == 0) g_indptr[n] = carry;
}

__global__ void k_fill(const int* __restrict__ src,
                       const int* __restrict__ dst, int E, int n) {
    int i = blockIdx.x * blockDim.x + threadIdx.x;
    if (i < E) {
        int d = dst[i];
        int s = src[i];
        d = max(0, min(n - 1, d));          // clamp: trap-proof
        s = max(0, min(n - 1, s));
        int p = atomicAdd(&g_cursor[d], 1);
        if (p >= 0 && p < EDGES_MAX) g_srcs[p] = s;
    }
}

// ---------------- fp32 tiled GEMM: C[M,N] = A[M,K] @ B[K,N] -----------------
// BM=BN=64, BK=16, 256 threads, 4x4 microtile.
// A operand: Aext if non-null, else g_agg1. C operand: c_sel==0 -> g_h1, else g_h2.
__global__ void __launch_bounds__(256) k_gemm(const float* __restrict__ Aext,
                                              const float* __restrict__ B,
                                              int c_sel,
                                              int M, int N, int K) {
    const float* A = Aext ? Aext : g_agg1;
    float* C = (c_sel == 0) ? g_h1 : g_h2;

    const int BM = 64, BN = 64, BK = 16;
    __shared__ __align__(16) float As[BK][BM];
    __shared__ __align__(16) float Bs[BK][BN];
    int tid = threadIdx.x;
    int tx = tid & 15, ty = tid >> 4;
    int rowBase = blockIdx.y * BM;
    int colBase = blockIdx.x * BN;

    float acc[4][4] = {};

    int ac = tid & 15;        // k within tile
    int ar = tid >> 4;        // row subgroup (stride 16)
    int bc = tid & 63;        // col
    int br = tid >> 6;        // k subgroup (stride 4)

    for (int k0 = 0; k0 < K; k0 += BK) {
        #pragma unroll
        for (int i = 0; i < 4; i++) {
            int r = ar + i * 16;
            int gr = rowBase + r;
            As[ac][r] = (gr < M) ? A[(size_t)gr * K + k0 + ac] : 0.0f;
        }
        #pragma unroll
        for (int i = 0; i < 4; i++) {
            int r = br + i * 4;
            Bs[r][bc] = B[(size_t)(k0 + r) * N + colBase + bc];
        }
        __syncthreads();
        #pragma unroll
        for (int k = 0; k < BK; k++) {
            float4 a = *reinterpret_cast<const float4*>(&As[k][ty * 4]);
            float4 b = *reinterpret_cast<const float4*>(&Bs[k][tx * 4]);
            float av[4] = {a.x, a.y, a.z, a.w};
            float bv[4] = {b.x, b.y, b.z, b.w};
            #pragma unroll
            for (int m = 0; m < 4; m++)
                #pragma unroll
                for (int n = 0; n < 4; n++)
                    acc[m][n] = fmaf(av[m], bv[n], acc[m][n]);
        }
        __syncthreads();
    }

    #pragma unroll
    for (int m = 0; m < 4; m++) {
        int gr = rowBase + ty * 4 + m;
        if (gr < M) {
            float4 o = make_float4(acc[m][0], acc[m][1], acc[m][2], acc[m][3]);
            *reinterpret_cast<float4*>(&C[(size_t)gr * N + colBase + tx * 4]) = o;
        }
    }
}

// ---------------- layer-1 aggregation (pull, no atomics) + bias + relu ------
__global__ void __launch_bounds__(HID) k_agg1(const float* __restrict__ b1) {
    int d = blockIdx.x;
    int j = threadIdx.x;  // 0..255
    float dd = g_dinv[d];
    // self loop contributes dd*dd*h1[d]; factor one dd out.
    float acc = dd * g_h1[(size_t)d * HID + j];
    int beg = g_indptr[d], end = g_indptr[d + 1];
    __shared__ int   sh_s[128];
    __shared__ float sh_w[128];
    for (int base = beg; base < end; base += 128) {
        int cnt = min(128, end - base);
        if (j < cnt) {
            int s = g_srcs[base + j];
            sh_s[j] = s;
            sh_w[j] = g_dinv[s];
        }
        __syncthreads();
        #pragma unroll 4
        for (int t = 0; t < cnt; t++)
            acc = fmaf(sh_w[t], g_h1[(size_t)sh_s[t] * HID + j], acc);
        __syncthreads();
    }
    float v = dd * acc + b1[j];
    g_agg1[(size_t)d * HID + j] = fmaxf(v, 0.0f);
}

// ---------------- layer-2 aggregation + bias + log_softmax (fused) ----------
__global__ void __launch_bounds__(OUTC) k_agg2_lsm(const float* __restrict__ b2,
                                                   float* __restrict__ out) {
    int d = blockIdx.x;
    int j = threadIdx.x;  // 0..63
    float dd = g_dinv[d];
    float acc = dd * g_h2[(size_t)d * OUTC + j];
    int beg = g_indptr[d], end = g_indptr[d + 1];
    __shared__ int   sh_s[64];
    __shared__ float sh_w[64];
    for (int base = beg; base < end; base += 64) {
        int cnt = min(64, end - base);
        if (j < cnt) {
            int s = g_srcs[base + j];
            sh_s[j] = s;
            sh_w[j] = g_dinv[s];
        }
        __syncthreads();
        #pragma unroll 4
        for (int t = 0; t < cnt; t++)
            acc = fmaf(sh_w[t], g_h2[(size_t)sh_s[t] * OUTC + j], acc);
        __syncthreads();
    }
    float v = dd * acc + b2[j];

    // log_softmax over the 64 lanes (2 warps)
    __shared__ float red[2];
    float m = v;
    #pragma unroll
    for (int o = 16; o; o >>= 1) m = fmaxf(m, __shfl_xor_sync(0xffffffffu, m, o));
    if ((j & 31) == 0) red[j >> 5] = m;
    __syncthreads();
    m = fmaxf(red[0], red[1]);
    __syncthreads();
    float e = expf(v - m);
    float s = e;
    #pragma unroll
    for (int o = 16; o; o >>= 1) s += __shfl_xor_sync(0xffffffffu, s, o);
    if ((j & 31) == 0) red[j >> 5] = s;
    __syncthreads();
    float tot = red[0] + red[1];
    out[(size_t)d * OUTC + j] = v - m - logf(tot);
}

// ---------------- entry -----------------------------------------------------
extern "C" void kernel_launch(void* const* d_in, const int* in_sizes, int n_in,
                              void* d_out, int out_size) {
    // Identify inputs by UNIQUE element counts (order-proof):
    //   x: 25,600,000   edge_index: 1,600,000 (int32!)
    //   W1: 131,072     b1: 256    W2: 16,384    b2: 64
    const float* x  = nullptr;
    const int*   ei = nullptr;
    const float* W1 = nullptr;
    const float* b1 = nullptr;
    const float* W2 = nullptr;
    const float* b2 = nullptr;

    for (int i = 0; i < n_in; i++) {
        long long s = in_sizes[i];
        if      (s == (long long)NODES_MAX * INC)   x  = (const float*)d_in[i];
        else if (s == 2LL * EDGES_MAX)              ei = (const int*)d_in[i];
        else if (s == (long long)INC * HID)         W1 = (const float*)d_in[i];
        else if (s == HID)                          b1 = (const float*)d_in[i];
        else if (s == (long long)HID * OUTC)        W2 = (const float*)d_in[i];
        else if (s == OUTC)                         b2 = (const float*)d_in[i];
    }
    // Positional fallback (reference setup_inputs dict order)
    if (!x  && n_in > 0) x  = (const float*)d_in[0];
    if (!ei && n_in > 1) ei = (const int*)d_in[1];
    if (!W1 && n_in > 2) W1 = (const float*)d_in[2];
    if (!b1 && n_in > 3) b1 = (const float*)d_in[3];
    if (!W2 && n_in > 4) W2 = (const float*)d_in[4];
    if (!b2 && n_in > 5) b2 = (const float*)d_in[5];

    float* out = (float*)d_out;

    int E  = EDGES_MAX;
    int Nn = out_size / OUTC;
    if (Nn > NODES_MAX) Nn = NODES_MAX;

    const int* src = ei;        // row 0
    const int* dst = ei + E;    // row 1

    int nb = (Nn + 255) / 256;
    int eb = (E + 255) / 256;

    // CSR build + degree norm
    k_zero_cnt<<<nb, 256>>>(Nn);
    k_count<<<eb, 256>>>(dst, E, Nn);
    k_dinv<<<nb, 256>>>(Nn);
    k_scan<<<1, 1024>>>(Nn);
    k_fill<<<eb, 256>>>(src, dst, E, Nn);

    // layer 1: h1 = x @ W1  (C -> g_h1)
    {
        dim3 grid(HID / 64, (Nn + 63) / 64);
        k_gemm<<<grid, 256>>>(x, W1, 0, Nn, HID, INC);
    }
    k_agg1<<<Nn, HID>>>(b1);

    // layer 2: h2 = g_agg1 @ W2  (A -> g_agg1 via null, C -> g_h2)
    {
        dim3 grid(OUTC / 64, (Nn + 63) / 64);
        k_gemm<<<grid, 256>>>((const float*)nullptr, W2, 1, Nn, OUTC, HID);
    }
    k_agg2_lsm<<<Nn, OUTC>>>(b2, out);
}

// round 5
// speedup vs baseline: 1.2271x; 1.2271x over previous
#include <cuda_runtime.h>
#include <math.h>

#define NODES_MAX 50000
#define HID 256
#define OUTC 64
#define INC 512
#define EDGES_MAX 800000

// ---------------- scratch (static __device__ per allocation rules) ----------
__device__ float g_h1[(size_t)NODES_MAX * HID];     // x @ W1
__device__ float g_agg1[(size_t)NODES_MAX * HID];   // relu(norm-agg(h1) + b1)
__device__ float g_h2[(size_t)NODES_MAX * OUTC];    // agg1 @ W2
__device__ float g_dinv[NODES_MAX];
__device__ int   g_cnt[NODES_MAX];
__device__ int   g_indptr[NODES_MAX + 1];
__device__ int   g_cursor[NODES_MAX];
__device__ int   g_srcs[EDGES_MAX];

// ---------------- graph preprocessing ---------------------------------------
__global__ void k_zero_cnt(int n) {
    int i = blockIdx.x * blockDim.x + threadIdx.x;
    if (i < n) g_cnt[i] = 0;
}

// edge_index is INT32 (JAX x64 disabled downcasts jnp.int64 -> int32).
__global__ void k_count(const int* __restrict__ dst, int E, int n) {
    int i = blockIdx.x * blockDim.x + threadIdx.x;
    if (i < E) {
        int d = dst[i];
        d = max(0, min(n - 1, d));          // clamp: trap-proof
        atomicAdd(&g_cnt[d], 1);
    }
}

// Fast single-block scan: each thread serially scans a contiguous chunk,
// one shuffle block-scan of thread totals, then writes prefixes + dinv.
__global__ void __launch_bounds__(1024) k_scan2(int n) {
    const int T = 1024;
    int tid = threadIdx.x;
    int chunk = (n + T - 1) / T;
    int beg = tid * chunk;
    int end = min(beg + chunk, n);

    int sum = 0;
    for (int i = beg; i < end; i++) sum += g_cnt[i];

    // block-wide exclusive scan of per-thread sums
    int lane = tid & 31, wid = tid >> 5;
    int v = sum;
    #pragma unroll
    for (int off = 1; off < 32; off <<= 1) {
        int t = __shfl_up_sync(0xffffffffu, v, off);
        if (lane >= off) v += t;
    }
    __shared__ int wsum[32];
    if (lane == 31) wsum[wid] = v;
    __syncthreads();
    if (wid == 0) {
        int w = wsum[lane];
        #pragma unroll
        for (int off = 1; off < 32; off <<= 1) {
            int t = __shfl_up_sync(0xffffffffu, w, off);
            if (lane >= off) w += t;
        }
        wsum[lane] = w;
    }
    __syncthreads();
    int excl = v - sum + (wid ? wsum[wid - 1] : 0);

    int run = excl;
    for (int i = beg; i < end; i++) {
        int c = g_cnt[i];
        g_indptr[i] = run;
        g_cursor[i] = run;
        g_dinv[i] = rsqrtf((float)(c + 1));   // +1 self loop (fused k_dinv)
        run += c;
    }
    if (tid == 0) g_indptr[n] = wsum[31];
}

__global__ void k_fill(const int* __restrict__ src,
                       const int* __restrict__ dst, int E, int n) {
    int i = blockIdx.x * blockDim.x + threadIdx.x;
    if (i < E) {
        int d = dst[i];
        int s = src[i];
        d = max(0, min(n - 1, d));          // clamp: trap-proof
        s = max(0, min(n - 1, s));
        int p = atomicAdd(&g_cursor[d], 1);
        if (p >= 0 && p < EDGES_MAX) g_srcs[p] = s;
    }
}

// ---------------- fp32 tiled GEMM: C[M,N] = A[M,K] @ B[K,N] -----------------
// Templated: BM x BN x BK tile, TM x TN microtile, 256 threads,
// float4 loads, register-prefetch K pipeline.
// Requires: N % BN == 0, K % BK == 0, BM*BK/4 == 256, BK % 4 == 0.
// A operand: Aext if non-null, else g_agg1. C: c_sel==0 -> g_h1, else g_h2.
template<int BM, int BN, int BK, int TM, int TN>
__global__ void __launch_bounds__(256) k_gemm(const float* __restrict__ Aext,
                                              const float* __restrict__ B,
                                              int c_sel,
                                              int M, int N, int K) {
    const float* A = Aext ? Aext : g_agg1;
    float* C = (c_sel == 0) ? g_h1 : g_h2;

    __shared__ __align__(16) float As[BK][BM];
    __shared__ __align__(16) float Bs[BK][BN];

    const int tid = threadIdx.x;
    const int rowBase = blockIdx.y * BM;
    const int colBase = blockIdx.x * BN;

    // A loader: one float4 per thread. BK/4 float4 per row.
    const int a_row = tid / (BK / 4);
    const int a_k   = (tid % (BK / 4)) * 4;
    const int a_gr  = rowBase + a_row;
    // B loader: B_V4 = BK*BN/4 float4 total (may be < 256).
    constexpr int B_V4 = BK * BN / 4;
    const int b_k  = tid / (BN / 4);
    const int b_c4 = (tid % (BN / 4)) * 4;
    const bool b_act = (B_V4 >= 256) || (tid < B_V4);

    // compute thread grid: (BM/TM) x (BN/TN) == 256
    const int tx = tid % (BN / TN);
    const int ty = tid / (BN / TN);

    float acc[TM][TN] = {};

    // preload tile 0
    float4 a_reg = make_float4(0.f, 0.f, 0.f, 0.f);
    float4 b_reg = make_float4(0.f, 0.f, 0.f, 0.f);
    if (a_gr < M) a_reg = *reinterpret_cast<const float4*>(&A[(size_t)a_gr * K + a_k]);
    if (b_act)    b_reg = *reinterpret_cast<const float4*>(&B[(size_t)b_k * N + colBase + b_c4]);
    As[a_k + 0][a_row] = a_reg.x;
    As[a_k + 1][a_row] = a_reg.y;
    As[a_k + 2][a_row] = a_reg.z;
    As[a_k + 3][a_row] = a_reg.w;
    if (b_act) *reinterpret_cast<float4*>(&Bs[b_k][b_c4]) = b_reg;
    __syncthreads();

    for (int k0 = BK; k0 <= K; k0 += BK) {
        float4 a_nxt, b_nxt;
        if (k0 < K) {
            a_nxt = make_float4(0.f, 0.f, 0.f, 0.f);
            if (a_gr < M)
                a_nxt = *reinterpret_cast<const float4*>(&A[(size_t)a_gr * K + k0 + a_k]);
            if (b_act)
                b_nxt = *reinterpret_cast<const float4*>(&B[(size_t)(k0 + b_k) * N + colBase + b_c4]);
        }

        #pragma unroll
        for (int k = 0; k < BK; k++) {
            float av[TM], bv[TN];
            #pragma unroll
            for (int i = 0; i < TM; i += 4)
                *reinterpret_cast<float4*>(&av[i]) =
                    *reinterpret_cast<const float4*>(&As[k][ty * TM + i]);
            #pragma unroll
            for (int j = 0; j < TN; j += 4)
                *reinterpret_cast<float4*>(&bv[j]) =
                    *reinterpret_cast<const float4*>(&Bs[k][tx * TN + j]);
            #pragma unroll
            for (int i = 0; i < TM; i++)
                #pragma unroll
                for (int j = 0; j < TN; j++)
                    acc[i][j] = fmaf(av[i], bv[j], acc[i][j]);
        }
        __syncthreads();

        if (k0 < K) {
            As[a_k + 0][a_row] = a_nxt.x;
            As[a_k + 1][a_row] = a_nxt.y;
            As[a_k + 2][a_row] = a_nxt.z;
            As[a_k + 3][a_row] = a_nxt.w;
            if (b_act) *reinterpret_cast<float4*>(&Bs[b_k][b_c4]) = b_nxt;
            __syncthreads();
        }
    }

    #pragma unroll
    for (int i = 0; i < TM; i++) {
        int gr = rowBase + ty * TM + i;
        if (gr < M) {
            #pragma unroll
            for (int j = 0; j < TN; j += 4) {
                float4 o = make_float4(acc[i][j], acc[i][j + 1], acc[i][j + 2], acc[i][j + 3]);
                *reinterpret_cast<float4*>(&C[(size_t)gr * N + colBase + tx * TN + j]) = o;
            }
        }
    }
}

// ---------------- layer-1 aggregation (pull, no atomics) + bias + relu ------
__global__ void __launch_bounds__(HID) k_agg1(const float* __restrict__ b1) {
    int d = blockIdx.x;
    int j = threadIdx.x;  // 0..255
    float dd = g_dinv[d];
    // self loop contributes dd*dd*h1[d]; factor one dd out.
    float acc = dd * g_h1[(size_t)d * HID + j];
    int beg = g_indptr[d], end = g_indptr[d + 1];
    __shared__ int   sh_s[128];
    __shared__ float sh_w[128];
    for (int base = beg; base < end; base += 128) {
        int cnt = min(128, end - base);
        if (j < cnt) {
            int s = g_srcs[base + j];
            sh_s[j] = s;
            sh_w[j] = g_dinv[s];
        }
        __syncthreads();
        #pragma unroll 4
        for (int t = 0; t < cnt; t++)
            acc = fmaf(sh_w[t], g_h1[(size_t)sh_s[t] * HID + j], acc);
        __syncthreads();
    }
    float v = dd * acc + b1[j];
    g_agg1[(size_t)d * HID + j] = fmaxf(v, 0.0f);
}

// ---------------- layer-2 aggregation + bias + log_softmax (fused) ----------
__global__ void __launch_bounds__(OUTC) k_agg2_lsm(const float* __restrict__ b2,
                                                   float* __restrict__ out) {
    int d = blockIdx.x;
    int j = threadIdx.x;  // 0..63
    float dd = g_dinv[d];
    float acc = dd * g_h2[(size_t)d * OUTC + j];
    int beg = g_indptr[d], end = g_indptr[d + 1];
    __shared__ int   sh_s[64];
    __shared__ float sh_w[64];
    for (int base = beg; base < end; base += 64) {
        int cnt = min(64, end - base);
        if (j < cnt) {
            int s = g_srcs[base + j];
            sh_s[j] = s;
            sh_w[j] = g_dinv[s];
        }
        __syncthreads();
        #pragma unroll 4
        for (int t = 0; t < cnt; t++)
            acc = fmaf(sh_w[t], g_h2[(size_t)sh_s[t] * OUTC + j], acc);
        __syncthreads();
    }
    float v = dd * acc + b2[j];

    // log_softmax over the 64 lanes (2 warps)
    __shared__ float red[2];
    float m = v;
    #pragma unroll
    for (int o = 16; o; o >>= 1) m = fmaxf(m, __shfl_xor_sync(0xffffffffu, m, o));
    if ((j & 31) == 0) red[j >> 5] = m;
    __syncthreads();
    m = fmaxf(red[0], red[1]);
    __syncthreads();
    float e = expf(v - m);
    float s = e;
    #pragma unroll
    for (int o = 16; o; o >>= 1) s += __shfl_xor_sync(0xffffffffu, s, o);
    if ((j & 31) == 0) red[j >> 5] = s;
    __syncthreads();
    float tot = red[0] + red[1];
    out[(size_t)d * OUTC + j] = v - m - logf(tot);
}

// ---------------- entry -----------------------------------------------------
extern "C" void kernel_launch(void* const* d_in, const int* in_sizes, int n_in,
                              void* d_out, int out_size) {
    // Identify inputs by UNIQUE element counts (order-proof):
    const float* x  = nullptr;
    const int*   ei = nullptr;
    const float* W1 = nullptr;
    const float* b1 = nullptr;
    const float* W2 = nullptr;
    const float* b2 = nullptr;

    for (int i = 0; i < n_in; i++) {
        long long s = in_sizes[i];
        if      (s == (long long)NODES_MAX * INC)   x  = (const float*)d_in[i];
        else if (s == 2LL * EDGES_MAX)              ei = (const int*)d_in[i];
        else if (s == (long long)INC * HID)         W1 = (const float*)d_in[i];
        else if (s == HID)                          b1 = (const float*)d_in[i];
        else if (s == (long long)HID * OUTC)        W2 = (const float*)d_in[i];
        else if (s == OUTC)                         b2 = (const float*)d_in[i];
    }
    if (!x  && n_in > 0) x  = (const float*)d_in[0];
    if (!ei && n_in > 1) ei = (const int*)d_in[1];
    if (!W1 && n_in > 2) W1 = (const float*)d_in[2];
    if (!b1 && n_in > 3) b1 = (const float*)d_in[3];
    if (!W2 && n_in > 4) W2 = (const float*)d_in[4];
    if (!b2 && n_in > 5) b2 = (const float*)d_in[5];

    float* out = (float*)d_out;

    int E  = EDGES_MAX;
    int Nn = out_size / OUTC;
    if (Nn > NODES_MAX) Nn = NODES_MAX;

    const int* src = ei;        // row 0
    const int* dst = ei + E;    // row 1

    int nb = (Nn + 255) / 256;
    int eb = (E + 255) / 256;

    // CSR build + degree norm
    k_zero_cnt<<<nb, 256>>>(Nn);
    k_count<<<eb, 256>>>(dst, E, Nn);
    k_scan2<<<1, 1024>>>(Nn);
    k_fill<<<eb, 256>>>(src, dst, E, Nn);

    // layer 1: h1 = x @ W1  (C -> g_h1)   [M=50000, N=256, K=512]
    {
        dim3 grid(HID / 128, (Nn + 127) / 128);
        k_gemm<128, 128, 8, 8, 8><<<grid, 256>>>(x, W1, 0, Nn, HID, INC);
    }
    k_agg1<<<Nn, HID>>>(b1);

    // layer 2: h2 = g_agg1 @ W2  [M=50000, N=64, K=256]
    {
        dim3 grid(OUTC / 64, (Nn + 127) / 128);
        k_gemm<128, 64, 8, 8, 4><<<grid, 256>>>((const float*)nullptr, W2, 1, Nn, OUTC, HID);
    }
    k_agg2_lsm<<<Nn, OUTC>>>(b2, out);
}

// round 7
// speedup vs baseline: 1.2517x; 1.0200x over previous
#include <cuda_runtime.h>
#include <math.h>
#include <mma.h>

using namespace nvcuda;

#define NODES_MAX 50000
#define M_PAD 50048          // 391 * 128, wmma epilogue padding
#define HID 256
#define OUTC 64
#define INC 512
#define EDGES_MAX 800000

// ---------------- scratch (static __device__ per allocation rules) ----------
__device__ float g_h1[(size_t)M_PAD * HID];         // x @ W1 (padded rows)
__device__ float g_agg1[(size_t)NODES_MAX * HID];   // relu(norm-agg(h1) + b1)
__device__ float g_h2[(size_t)NODES_MAX * OUTC];    // agg1 @ W2
__device__ float g_dinv[NODES_MAX];
__device__ int   g_cnt[NODES_MAX];
__device__ int   g_indptr[NODES_MAX + 1];
__device__ int   g_cursor[NODES_MAX];
__device__ int   g_srcs[EDGES_MAX];

// ---------------- graph preprocessing ---------------------------------------
__global__ void k_zero_cnt(int n) {
    int i = blockIdx.x * blockDim.x + threadIdx.x;
    if (i < n) g_cnt[i] = 0;
}

// edge_index is INT32.
__global__ void k_count(const int* __restrict__ dst, int E, int n) {
    int i = blockIdx.x * blockDim.x + threadIdx.x;
    if (i < E) {
        int d = dst[i];
        d = max(0, min(n - 1, d));
        atomicAdd(&g_cnt[d], 1);
    }
}

// Fast single-block scan + fused dinv.
__global__ void __launch_bounds__(1024) k_scan2(int n) {
    const int T = 1024;
    int tid = threadIdx.x;
    int chunk = (n + T - 1) / T;
    int beg = tid * chunk;
    int end = min(beg + chunk, n);

    int sum = 0;
    for (int i = beg; i < end; i++) sum += g_cnt[i];

    int lane = tid & 31, wid = tid >> 5;
    int v = sum;
    #pragma unroll
    for (int off = 1; off < 32; off <<= 1) {
        int t = __shfl_up_sync(0xffffffffu, v, off);
        if (lane >= off) v += t;
    }
    __shared__ int wsum[32];
    if (lane == 31) wsum[wid] = v;
    __syncthreads();
    if (wid == 0) {
        int w = wsum[lane];
        #pragma unroll
        for (int off = 1; off < 32; off <<= 1) {
            int t = __shfl_up_sync(0xffffffffu, w, off);
            if (lane >= off) w += t;
        }
        wsum[lane] = w;
    }
    __syncthreads();
    int excl = v - sum + (wid ? wsum[wid - 1] : 0);

    int run = excl;
    for (int i = beg; i < end; i++) {
        int c = g_cnt[i];
        g_indptr[i] = run;
        g_cursor[i] = run;
        g_dinv[i] = rsqrtf((float)(c + 1));
        run += c;
    }
    if (tid == 0) g_indptr[n] = wsum[31];
}

__global__ void k_fill(const int* __restrict__ src,
                       const int* __restrict__ dst, int E, int n) {
    int i = blockIdx.x * blockDim.x + threadIdx.x;
    if (i < E) {
        int d = dst[i];
        int s = src[i];
        d = max(0, min(n - 1, d));
        s = max(0, min(n - 1, s));
        int p = atomicAdd(&g_cursor[d], 1);
        if (p >= 0 && p < EDGES_MAX) g_srcs[p] = s;
    }
}

// ---------------- GEMM1: tf32 wmma, C -> g_h1 -------------------------------
// BM=128, BN=128, BK=16; 8 warps (4 rows x 2 cols), warp tile 32x64.
// A guarded by row<M; C rows padded to M_PAD so stores are unguarded.
__global__ void __launch_bounds__(256) k_gemm1_wmma(const float* __restrict__ A,
                                                    const float* __restrict__ B,
                                                    int M, int N, int K) {
    const int BM = 128, BN = 128, BK = 16;
    __shared__ __align__(16) float As[BM][BK + 4];   // 128 x 20
    __shared__ __align__(16) float Bs[BK][BN + 4];   // 16 x 132

    const int tid = threadIdx.x;
    const int wid = tid >> 5;
    const int warpRow = wid >> 1;      // 0..3 -> m offset *32
    const int warpCol = wid & 1;       // 0..1 -> n offset *64
    const int rowBase = blockIdx.y * BM;
    const int colBase = blockIdx.x * BN;

    // A loader: 2 float4 per thread. row = tid/4 (+64), col4 = (tid%4)*4
    const int a_r0 = tid >> 2;
    const int a_c  = (tid & 3) * 4;
    // B loader: 2 float4 per thread. row = tid/32 (+8), col4 = (tid%32)*4
    const int b_r0 = tid >> 5;
    const int b_c  = (tid & 31) * 4;

    wmma::fragment<wmma::accumulator, 16, 16, 8, float> acc[2][4];
    #pragma unroll
    for (int i = 0; i < 2; i++)
        #pragma unroll
        for (int j = 0; j < 4; j++)
            wmma::fill_fragment(acc[i][j], 0.0f);

    for (int k0 = 0; k0 < K; k0 += BK) {
        // stage A tile (guarded)
        #pragma unroll
        for (int h = 0; h < 2; h++) {
            int r = a_r0 + h * 64;
            int gr = rowBase + r;
            float4 vq = make_float4(0.f, 0.f, 0.f, 0.f);
            if (gr < M)
                vq = *reinterpret_cast<const float4*>(&A[(size_t)gr * K + k0 + a_c]);
            As[r][a_c + 0] = vq.x;
            As[r][a_c + 1] = vq.y;
            As[r][a_c + 2] = vq.z;
            As[r][a_c + 3] = vq.w;
        }
        // stage B tile (K,N exact multiples — unguarded)
        #pragma unroll
        for (int h = 0; h < 2; h++) {
            int r = b_r0 + h * 8;
            float4 vq = *reinterpret_cast<const float4*>(&B[(size_t)(k0 + r) * N + colBase + b_c]);
            *reinterpret_cast<float4*>(&Bs[r][b_c]) = vq;
        }
        __syncthreads();

        #pragma unroll
        for (int k8 = 0; k8 < BK; k8 += 8) {
            wmma::fragment<wmma::matrix_a, 16, 16, 8, wmma::precision::tf32, wmma::row_major> af[2];
            wmma::fragment<wmma::matrix_b, 16, 16, 8, wmma::precision::tf32, wmma::row_major> bf[4];
            #pragma unroll
            for (int i = 0; i < 2; i++) {
                wmma::load_matrix_sync(af[i], &As[warpRow * 32 + i * 16][k8], BK + 4);
                #pragma unroll
                for (int t = 0; t < af[i].num_elements; t++)
                    af[i].x[t] = wmma::__float_to_tf32(af[i].x[t]);
            }
            #pragma unroll
            for (int j = 0; j < 4; j++) {
                wmma::load_matrix_sync(bf[j], &Bs[k8][warpCol * 64 + j * 16], BN + 4);
                #pragma unroll
                for (int t = 0; t < bf[j].num_elements; t++)
                    bf[j].x[t] = wmma::__float_to_tf32(bf[j].x[t]);
            }
            #pragma unroll
            for (int i = 0; i < 2; i++)
                #pragma unroll
                for (int j = 0; j < 4; j++)
                    wmma::mma_sync(acc[i][j], af[i], bf[j], acc[i][j]);
        }
        __syncthreads();
    }

    #pragma unroll
    for (int i = 0; i < 2; i++) {
        int r0 = rowBase + warpRow * 32 + i * 16;
        #pragma unroll
        for (int j = 0; j < 4; j++) {
            int c0 = colBase + warpCol * 64 + j * 16;
            wmma::store_matrix_sync(&g_h1[(size_t)r0 * N + c0], acc[i][j], N,
                                    wmma::mem_row_major);
        }
    }
}

// ---------------- fp32 SIMT GEMM (layer 2): C=g_h2 = g_agg1 @ B -------------
template<int BM, int BN, int BK, int TM, int TN>
__global__ void __launch_bounds__(256) k_gemm(const float* __restrict__ B,
                                              int M, int N, int K) {
    const float* A = g_agg1;
    float* C = g_h2;

    __shared__ __align__(16) float As[BK][BM];
    __shared__ __align__(16) float Bs[BK][BN];

    const int tid = threadIdx.x;
    const int rowBase = blockIdx.y * BM;
    const int colBase = blockIdx.x * BN;

    const int a_row = tid / (BK / 4);
    const int a_k   = (tid % (BK / 4)) * 4;
    const int a_gr  = rowBase + a_row;
    constexpr int B_V4 = BK * BN / 4;
    const int b_k  = tid / (BN / 4);
    const int b_c4 = (tid % (BN / 4)) * 4;
    const bool b_act = (B_V4 >= 256) || (tid < B_V4);

    const int tx = tid % (BN / TN);
    const int ty = tid / (BN / TN);

    float acc[TM][TN] = {};

    float4 a_reg = make_float4(0.f, 0.f, 0.f, 0.f);
    float4 b_reg = make_float4(0.f, 0.f, 0.f, 0.f);
    if (a_gr < M) a_reg = *reinterpret_cast<const float4*>(&A[(size_t)a_gr * K + a_k]);
    if (b_act)    b_reg = *reinterpret_cast<const float4*>(&B[(size_t)b_k * N + colBase + b_c4]);
    As[a_k + 0][a_row] = a_reg.x;
    As[a_k + 1][a_row] = a_reg.y;
    As[a_k + 2][a_row] = a_reg.z;
    As[a_k + 3][a_row] = a_reg.w;
    if (b_act) *reinterpret_cast<float4*>(&Bs[b_k][b_c4]) = b_reg;
    __syncthreads();

    for (int k0 = BK; k0 <= K; k0 += BK) {
        float4 a_nxt, b_nxt;
        if (k0 < K) {
            a_nxt = make_float4(0.f, 0.f, 0.f, 0.f);
            if (a_gr < M)
                a_nxt = *reinterpret_cast<const float4*>(&A[(size_t)a_gr * K + k0 + a_k]);
            if (b_act)
                b_nxt = *reinterpret_cast<const float4*>(&B[(size_t)(k0 + b_k) * N + colBase + b_c4]);
        }

        #pragma unroll
        for (int k = 0; k < BK; k++) {
            float av[TM], bv[TN];
            #pragma unroll
            for (int i = 0; i < TM; i += 4)
                *reinterpret_cast<float4*>(&av[i]) =
                    *reinterpret_cast<const float4*>(&As[k][ty * TM + i]);
            #pragma unroll
            for (int j = 0; j < TN; j += 4)
                *reinterpret_cast<float4*>(&bv[j]) =
                    *reinterpret_cast<const float4*>(&Bs[k][tx * TN + j]);
            #pragma unroll
            for (int i = 0; i < TM; i++)
                #pragma unroll
                for (int j = 0; j < TN; j++)
                    acc[i][j] = fmaf(av[i], bv[j], acc[i][j]);
        }
        __syncthreads();

        if (k0 < K) {
            As[a_k + 0][a_row] = a_nxt.x;
            As[a_k + 1][a_row] = a_nxt.y;
            As[a_k + 2][a_row] = a_nxt.z;
            As[a_k + 3][a_row] = a_nxt.w;
            if (b_act) *reinterpret_cast<float4*>(&Bs[b_k][b_c4]) = b_nxt;
            __syncthreads();
        }
    }

    #pragma unroll
    for (int i = 0; i < TM; i++) {
        int gr = rowBase + ty * TM + i;
        if (gr < M) {
            #pragma unroll
            for (int j = 0; j < TN; j += 4) {
                float4 o = make_float4(acc[i][j], acc[i][j + 1], acc[i][j + 2], acc[i][j + 3]);
                *reinterpret_cast<float4*>(&C[(size_t)gr * N + colBase + tx * TN + j]) = o;
            }
        }
    }
}

// ---------------- layer-1 aggregation (pull) + bias + relu ------------------
__global__ void __launch_bounds__(HID) k_agg1(const float* __restrict__ b1) {
    int d = blockIdx.x;
    int j = threadIdx.x;
    float dd = g_dinv[d];
    float acc = dd * g_h1[(size_t)d * HID + j];
    int beg = g_indptr[d], end = g_indptr[d + 1];
    __shared__ int   sh_s[128];
    __shared__ float sh_w[128];
    for (int base = beg; base < end; base += 128) {
        int cnt = min(128, end - base);
        if (j < cnt) {
            int s = g_srcs[base + j];
            sh_s[j] = s;
            sh_w[j] = g_dinv[s];
        }
        __syncthreads();
        #pragma unroll 4
        for (int t = 0; t < cnt; t++)
            acc = fmaf(sh_w[t], g_h1[(size_t)sh_s[t] * HID + j], acc);
        __syncthreads();
    }
    float v = dd * acc + b1[j];
    g_agg1[(size_t)d * HID + j] = fmaxf(v, 0.0f);
}

// ---------------- layer-2 aggregation + bias + log_softmax ------------------
__global__ void __launch_bounds__(OUTC) k_agg2_lsm(const float* __restrict__ b2,
                                                   float* __restrict__ out) {
    int d = blockIdx.x;
    int j = threadIdx.x;
    float dd = g_dinv[d];
    float acc = dd * g_h2[(size_t)d * OUTC + j];
    int beg = g_indptr[d], end = g_indptr[d + 1];
    __shared__ int   sh_s[64];
    __shared__ float sh_w[64];
    for (int base = beg; base < end; base += 64) {
        int cnt = min(64, end - base);
        if (j < cnt) {
            int s = g_srcs[base + j];
            sh_s[j] = s;
            sh_w[j] = g_dinv[s];
        }
        __syncthreads();
        #pragma unroll 4
        for (int t = 0; t < cnt; t++)
            acc = fmaf(sh_w[t], g_h2[(size_t)sh_s[t] * OUTC + j], acc);
        __syncthreads();
    }
    float v = dd * acc + b2[j];

    __shared__ float red[2];
    float m = v;
    #pragma unroll
    for (int o = 16; o; o >>= 1) m = fmaxf(m, __shfl_xor_sync(0xffffffffu, m, o));
    if ((j & 31) == 0) red[j >> 5] = m;
    __syncthreads();
    m = fmaxf(red[0], red[1]);
    __syncthreads();
    float e = expf(v - m);
    float s = e;
    #pragma unroll
    for (int o = 16; o; o >>= 1) s += __shfl_xor_sync(0xffffffffu, s, o);
    if ((j & 31) == 0) red[j >> 5] = s;
    __syncthreads();
    float tot = red[0] + red[1];
    out[(size_t)d * OUTC + j] = v - m - logf(tot);
}

// ---------------- entry -----------------------------------------------------
extern "C" void kernel_launch(void* const* d_in, const int* in_sizes, int n_in,
                              void* d_out, int out_size) {
    const float* x  = nullptr;
    const int*   ei = nullptr;
    const float* W1 = nullptr;
    const float* b1 = nullptr;
    const float* W2 = nullptr;
    const float* b2 = nullptr;

    for (int i = 0; i < n_in; i++) {
        long long s = in_sizes[i];
        if      (s == (long long)NODES_MAX * INC)   x  = (const float*)d_in[i];
        else if (s == 2LL * EDGES_MAX)              ei = (const int*)d_in[i];
        else if (s == (long long)INC * HID)         W1 = (const float*)d_in[i];
        else if (s == HID)                          b1 = (const float*)d_in[i];
        else if (s == (long long)HID * OUTC)        W2 = (const float*)d_in[i];
        else if (s == OUTC)                         b2 = (const float*)d_in[i];
    }
    if (!x  && n_in > 0) x  = (const float*)d_in[0];
    if (!ei && n_in > 1) ei = (const int*)d_in[1];
    if (!W1 && n_in > 2) W1 = (const float*)d_in[2];
    if (!b1 && n_in > 3) b1 = (const float*)d_in[3];
    if (!W2 && n_in > 4) W2 = (const float*)d_in[4];
    if (!b2 && n_in > 5) b2 = (const float*)d_in[5];

    float* out = (float*)d_out;

    int E  = EDGES_MAX;
    int Nn = out_size / OUTC;
    if (Nn > NODES_MAX) Nn = NODES_MAX;

    const int* src = ei;
    const int* dst = ei + E;

    int nb = (Nn + 255) / 256;
    int eb = (E + 255) / 256;

    k_zero_cnt<<<nb, 256>>>(Nn);
    k_count<<<eb, 256>>>(dst, E, Nn);
    k_scan2<<<1, 1024>>>(Nn);
    k_fill<<<eb, 256>>>(src, dst, E, Nn);

    // layer 1: h1 = x @ W1 via tf32 tensor cores
    {
        dim3 grid(HID / 128, (Nn + 127) / 128);
        k_gemm1_wmma<<<grid, 256>>>(x, W1, Nn, HID, INC);
    }
    k_agg1<<<Nn, HID>>>(b1);

    // layer 2: h2 = g_agg1 @ W2 (SIMT fp32)
    {
        dim3 grid(OUTC / 64, (Nn + 127) / 128);
        k_gemm<128, 64, 8, 8, 4><<<grid, 256>>>(W2, Nn, OUTC, HID);
    }
    k_agg2_lsm<<<Nn, OUTC>>>(b2, out);
}

// round 9
// speedup vs baseline: 1.3708x; 1.0952x over previous
#include <cuda_runtime.h>
#include <math.h>
#include <mma.h>

using namespace nvcuda;

#define NODES_MAX 50000
#define M_PAD 50048          // 391 * 128, wmma epilogue padding
#define HID 256
#define OUTC 64
#define INC 512
#define EDGES_MAX 800000

// ---------------- scratch (static __device__ per allocation rules) ----------
__device__ float g_h1[(size_t)M_PAD * HID];         // x @ W1 (padded rows)
__device__ float g_agg1[(size_t)NODES_MAX * HID];   // relu(norm-agg(h1) + b1)
__device__ float g_h2[(size_t)NODES_MAX * OUTC];    // agg1 @ W2
__device__ float g_dinv[NODES_MAX];
__device__ int   g_cnt[NODES_MAX];
__device__ int   g_indptr[NODES_MAX + 1];
__device__ int   g_cursor[NODES_MAX];
__device__ int   g_srcs[EDGES_MAX];

// ---------------- graph preprocessing ---------------------------------------
__global__ void k_zero_cnt(int n) {
    int i = blockIdx.x * blockDim.x + threadIdx.x;
    if (i < n) g_cnt[i] = 0;
}

__global__ void k_count(const int* __restrict__ dst, int E, int n) {
    int i = blockIdx.x * blockDim.x + threadIdx.x;
    if (i < E) {
        int d = dst[i];
        d = max(0, min(n - 1, d));
        atomicAdd(&g_cnt[d], 1);
    }
}

__global__ void __launch_bounds__(1024) k_scan2(int n) {
    const int T = 1024;
    int tid = threadIdx.x;
    int chunk = (n + T - 1) / T;
    int beg = tid * chunk;
    int end = min(beg + chunk, n);

    int sum = 0;
    for (int i = beg; i < end; i++) sum += g_cnt[i];

    int lane = tid & 31, wid = tid >> 5;
    int v = sum;
    #pragma unroll
    for (int off = 1; off < 32; off <<= 1) {
        int t = __shfl_up_sync(0xffffffffu, v, off);
        if (lane >= off) v += t;
    }
    __shared__ int wsum[32];
    if (lane == 31) wsum[wid] = v;
    __syncthreads();
    if (wid == 0) {
        int w = wsum[lane];
        #pragma unroll
        for (int off = 1; off < 32; off <<= 1) {
            int t = __shfl_up_sync(0xffffffffu, w, off);
            if (lane >= off) w += t;
        }
        wsum[lane] = w;
    }
    __syncthreads();
    int excl = v - sum + (wid ? wsum[wid - 1] : 0);

    int run = excl;
    for (int i = beg; i < end; i++) {
        int c = g_cnt[i];
        g_indptr[i] = run;
        g_cursor[i] = run;
        g_dinv[i] = rsqrtf((float)(c + 1));
        run += c;
    }
    if (tid == 0) g_indptr[n] = wsum[31];
}

__global__ void k_fill(const int* __restrict__ src,
                       const int* __restrict__ dst, int E, int n) {
    int i = blockIdx.x * blockDim.x + threadIdx.x;
    if (i < E) {
        int d = dst[i];
        int s = src[i];
        d = max(0, min(n - 1, d));
        s = max(0, min(n - 1, s));
        int p = atomicAdd(&g_cursor[d], 1);
        if (p >= 0 && p < EDGES_MAX) g_srcs[p] = s;
    }
}

// ---------------- GEMM1: tf32 wmma v2, C -> g_h1 ----------------------------
// BM=128, BN=128, BK=32. 8 warps as 2 rows x 4 cols; warp tile 64x32
// (4x2 m16n16k8 atoms). tf32 pre-rounding in staging; register-prefetch
// pipeline (2 syncs per 32-K slab). Static smem 35.3 KB.
__global__ void __launch_bounds__(256) k_gemm1_wmma(const float* __restrict__ A,
                                                    const float* __restrict__ B,
                                                    int M, int N, int K) {
    const int BM = 128, BN = 128, BK = 32;
    const int LDA = BK + 4;   // 36 floats: row base 144B (16B-aligned)
    const int LDB = BN + 4;   // 132 floats: row base 528B (16B-aligned)
    __shared__ __align__(16) float As[BM][LDA];
    __shared__ __align__(16) float Bs[BK][LDB];

    const int tid = threadIdx.x;
    const int wid = tid >> 5;
    const int warpRow = wid >> 2;      // 0..1  -> m offset *64
    const int warpCol = wid & 3;       // 0..3  -> n offset *32
    const int rowBase = blockIdx.y * BM;
    const int colBase = blockIdx.x * BN;

    // A loader: row = tid/8 (+32 per pass, 4 passes), col4 = (tid%8)*4
    const int a_r0 = tid >> 3;
    const int a_c  = (tid & 7) * 4;
    // B loader: row = tid/32 (+8 per pass, 4 passes), col4 = (tid%32)*4
    const int b_r0 = tid >> 5;
    const int b_c  = (tid & 31) * 4;

    wmma::fragment<wmma::accumulator, 16, 16, 8, float> acc[4][2];
    #pragma unroll
    for (int i = 0; i < 4; i++)
        #pragma unroll
        for (int j = 0; j < 2; j++)
            wmma::fill_fragment(acc[i][j], 0.0f);

    float4 a_pf[4], b_pf[4];

    // ---- load tile 0 into regs ----
    #pragma unroll
    for (int h = 0; h < 4; h++) {
        int gr = rowBase + a_r0 + h * 32;
        a_pf[h] = make_float4(0.f, 0.f, 0.f, 0.f);
        if (gr < M) a_pf[h] = *reinterpret_cast<const float4*>(&A[(size_t)gr * K + a_c]);
        b_pf[h] = *reinterpret_cast<const float4*>(&B[(size_t)(b_r0 + h * 8) * N + colBase + b_c]);
    }
    // ---- stage tile 0 (pre-round to tf32) ----
    #pragma unroll
    for (int h = 0; h < 4; h++) {
        float4 va = a_pf[h];
        va.x = wmma::__float_to_tf32(va.x);  va.y = wmma::__float_to_tf32(va.y);
        va.z = wmma::__float_to_tf32(va.z);  va.w = wmma::__float_to_tf32(va.w);
        *reinterpret_cast<float4*>(&As[a_r0 + h * 32][a_c]) = va;
        float4 vb = b_pf[h];
        vb.x = wmma::__float_to_tf32(vb.x);  vb.y = wmma::__float_to_tf32(vb.y);
        vb.z = wmma::__float_to_tf32(vb.z);  vb.w = wmma::__float_to_tf32(vb.w);
        *reinterpret_cast<float4*>(&Bs[b_r0 + h * 8][b_c]) = vb;
    }
    __syncthreads();

    const int nt = K / BK;
    for (int kt = 0; kt < nt; kt++) {
        // prefetch next tile into regs (overlaps with MMA below)
        if (kt + 1 < nt) {
            int k0 = (kt + 1) * BK;
            #pragma unroll
            for (int h = 0; h < 4; h++) {
                int gr = rowBase + a_r0 + h * 32;
                a_pf[h] = make_float4(0.f, 0.f, 0.f, 0.f);
                if (gr < M)
                    a_pf[h] = *reinterpret_cast<const float4*>(&A[(size_t)gr * K + k0 + a_c]);
                b_pf[h] = *reinterpret_cast<const float4*>(&B[(size_t)(k0 + b_r0 + h * 8) * N + colBase + b_c]);
            }
        }

        // MMA over current tile: 4 k8 steps
        #pragma unroll
        for (int k8 = 0; k8 < BK; k8 += 8) {
            wmma::fragment<wmma::matrix_a, 16, 16, 8, wmma::precision::tf32, wmma::row_major> af[4];
            wmma::fragment<wmma::matrix_b, 16, 16, 8, wmma::precision::tf32, wmma::row_major> bf[2];
            #pragma unroll
            for (int i = 0; i < 4; i++)
                wmma::load_matrix_sync(af[i], &As[warpRow * 64 + i * 16][k8], LDA);
            #pragma unroll
            for (int j = 0; j < 2; j++)
                wmma::load_matrix_sync(bf[j], &Bs[k8][warpCol * 32 + j * 16], LDB);
            #pragma unroll
            for (int i = 0; i < 4; i++)
                #pragma unroll
                for (int j = 0; j < 2; j++)
                    wmma::mma_sync(acc[i][j], af[i], bf[j], acc[i][j]);
        }
        __syncthreads();

        if (kt + 1 < nt) {
            #pragma unroll
            for (int h = 0; h < 4; h++) {
                float4 va = a_pf[h];
                va.x = wmma::__float_to_tf32(va.x);  va.y = wmma::__float_to_tf32(va.y);
                va.z = wmma::__float_to_tf32(va.z);  va.w = wmma::__float_to_tf32(va.w);
                *reinterpret_cast<float4*>(&As[a_r0 + h * 32][a_c]) = va;
                float4 vb = b_pf[h];
                vb.x = wmma::__float_to_tf32(vb.x);  vb.y = wmma::__float_to_tf32(vb.y);
                vb.z = wmma::__float_to_tf32(vb.z);  vb.w = wmma::__float_to_tf32(vb.w);
                *reinterpret_cast<float4*>(&Bs[b_r0 + h * 8][b_c]) = vb;
            }
            __syncthreads();
        }
    }

    // epilogue: unguarded (g_h1 rows padded to M_PAD)
    #pragma unroll
    for (int i = 0; i < 4; i++) {
        int r0 = rowBase + warpRow * 64 + i * 16;
        #pragma unroll
        for (int j = 0; j < 2; j++) {
            int c0 = colBase + warpCol * 32 + j * 16;
            wmma::store_matrix_sync(&g_h1[(size_t)r0 * N + c0], acc[i][j], N,
                                    wmma::mem_row_major);
        }
    }
}

// ---------------- fp32 SIMT GEMM (layer 2): C=g_h2 = g_agg1 @ B -------------
template<int BM, int BN, int BK, int TM, int TN>
__global__ void __launch_bounds__(256) k_gemm(const float* __restrict__ B,
                                              int M, int N, int K) {
    const float* A = g_agg1;
    float* C = g_h2;

    __shared__ __align__(16) float As[BK][BM];
    __shared__ __align__(16) float Bs[BK][BN];

    const int tid = threadIdx.x;
    const int rowBase = blockIdx.y * BM;
    const int colBase = blockIdx.x * BN;

    const int a_row = tid / (BK / 4);
    const int a_k   = (tid % (BK / 4)) * 4;
    const int a_gr  = rowBase + a_row;
    constexpr int B_V4 = BK * BN / 4;
    const int b_k  = tid / (BN / 4);
    const int b_c4 = (tid % (BN / 4)) * 4;
    const bool b_act = (B_V4 >= 256) || (tid < B_V4);

    const int tx = tid % (BN / TN);
    const int ty = tid / (BN / TN);

    float acc[TM][TN] = {};

    float4 a_reg = make_float4(0.f, 0.f, 0.f, 0.f);
    float4 b_reg = make_float4(0.f, 0.f, 0.f, 0.f);
    if (a_gr < M) a_reg = *reinterpret_cast<const float4*>(&A[(size_t)a_gr * K + a_k]);
    if (b_act)    b_reg = *reinterpret_cast<const float4*>(&B[(size_t)b_k * N + colBase + b_c4]);
    As[a_k + 0][a_row] = a_reg.x;
    As[a_k + 1][a_row] = a_reg.y;
    As[a_k + 2][a_row] = a_reg.z;
    As[a_k + 3][a_row] = a_reg.w;
    if (b_act) *reinterpret_cast<float4*>(&Bs[b_k][b_c4]) = b_reg;
    __syncthreads();

    for (int k0 = BK; k0 <= K; k0 += BK) {
        float4 a_nxt, b_nxt;
        if (k0 < K) {
            a_nxt = make_float4(0.f, 0.f, 0.f, 0.f);
            if (a_gr < M)
                a_nxt = *reinterpret_cast<const float4*>(&A[(size_t)a_gr * K + k0 + a_k]);
            if (b_act)
                b_nxt = *reinterpret_cast<const float4*>(&B[(size_t)(k0 + b_k) * N + colBase + b_c4]);
        }

        #pragma unroll
        for (int k = 0; k < BK; k++) {
            float av[TM], bv[TN];
            #pragma unroll
            for (int i = 0; i < TM; i += 4)
                *reinterpret_cast<float4*>(&av[i]) =
                    *reinterpret_cast<const float4*>(&As[k][ty * TM + i]);
            #pragma unroll
            for (int j = 0; j < TN; j += 4)
                *reinterpret_cast<float4*>(&bv[j]) =
                    *reinterpret_cast<const float4*>(&Bs[k][tx * TN + j]);
            #pragma unroll
            for (int i = 0; i < TM; i++)
                #pragma unroll
                for (int j = 0; j < TN; j++)
                    acc[i][j] = fmaf(av[i], bv[j], acc[i][j]);
        }
        __syncthreads();

        if (k0 < K) {
            As[a_k + 0][a_row] = a_nxt.x;
            As[a_k + 1][a_row] = a_nxt.y;
            As[a_k + 2][a_row] = a_nxt.z;
            As[a_k + 3][a_row] = a_nxt.w;
            if (b_act) *reinterpret_cast<float4*>(&Bs[b_k][b_c4]) = b_nxt;
            __syncthreads();
        }
    }

    #pragma unroll
    for (int i = 0; i < TM; i++) {
        int gr = rowBase + ty * TM + i;
        if (gr < M) {
            #pragma unroll
            for (int j = 0; j < TN; j += 4) {
                float4 o = make_float4(acc[i][j], acc[i][j + 1], acc[i][j + 2], acc[i][j + 3]);
                *reinterpret_cast<float4*>(&C[(size_t)gr * N + colBase + tx * TN + j]) = o;
            }
        }
    }
}

// ---------------- layer-1 aggregation (pull) + bias + relu ------------------
__global__ void __launch_bounds__(HID) k_agg1(const float* __restrict__ b1) {
    int d = blockIdx.x;
    int j = threadIdx.x;
    float dd = g_dinv[d];
    float acc = dd * g_h1[(size_t)d * HID + j];
    int beg = g_indptr[d], end = g_indptr[d + 1];
    __shared__ int   sh_s[128];
    __shared__ float sh_w[128];
    for (int base = beg; base < end; base += 128) {
        int cnt = min(128, end - base);
        if (j < cnt) {
            int s = g_srcs[base + j];
            sh_s[j] = s;
            sh_w[j] = g_dinv[s];
        }
        __syncthreads();
        #pragma unroll 4
        for (int t = 0; t < cnt; t++)
            acc = fmaf(sh_w[t], g_h1[(size_t)sh_s[t] * HID + j], acc);
        __syncthreads();
    }
    float v = dd * acc + b1[j];
    g_agg1[(size_t)d * HID + j] = fmaxf(v, 0.0f);
}

// ---------------- layer-2 aggregation + bias + log_softmax ------------------
__global__ void __launch_bounds__(OUTC) k_agg2_lsm(const float* __restrict__ b2,
                                                   float* __restrict__ out) {
    int d = blockIdx.x;
    int j = threadIdx.x;
    float dd = g_dinv[d];
    float acc = dd * g_h2[(size_t)d * OUTC + j];
    int beg = g_indptr[d], end = g_indptr[d + 1];
    __shared__ int   sh_s[64];
    __shared__ float sh_w[64];
    for (int base = beg; base < end; base += 64) {
        int cnt = min(64, end - base);
        if (j < cnt) {
            int s = g_srcs[base + j];
            sh_s[j] = s;
            sh_w[j] = g_dinv[s];
        }
        __syncthreads();
        #pragma unroll 4
        for (int t = 0; t < cnt; t++)
            acc = fmaf(sh_w[t], g_h2[(size_t)sh_s[t] * OUTC + j], acc);
        __syncthreads();
    }
    float v = dd * acc + b2[j];

    __shared__ float red[2];
    float m = v;
    #pragma unroll
    for (int o = 16; o; o >>= 1) m = fmaxf(m, __shfl_xor_sync(0xffffffffu, m, o));
    if ((j & 31) == 0) red[j >> 5] = m;
    __syncthreads();
    m = fmaxf(red[0], red[1]);
    __syncthreads();
    float e = expf(v - m);
    float s = e;
    #pragma unroll
    for (int o = 16; o; o >>= 1) s += __shfl_xor_sync(0xffffffffu, s, o);
    if ((j & 31) == 0) red[j >> 5] = s;
    __syncthreads();
    float tot = red[0] + red[1];
    out[(size_t)d * OUTC + j] = v - m - logf(tot);
}

// ---------------- entry -----------------------------------------------------
extern "C" void kernel_launch(void* const* d_in, const int* in_sizes, int n_in,
                              void* d_out, int out_size) {
    const float* x  = nullptr;
    const int*   ei = nullptr;
    const float* W1 = nullptr;
    const float* b1 = nullptr;
    const float* W2 = nullptr;
    const float* b2 = nullptr;

    for (int i = 0; i < n_in; i++) {
        long long s = in_sizes[i];
        if      (s == (long long)NODES_MAX * INC)   x  = (const float*)d_in[i];
        else if (s == 2LL * EDGES_MAX)              ei = (const int*)d_in[i];
        else if (s == (long long)INC * HID)         W1 = (const float*)d_in[i];
        else if (s == HID)                          b1 = (const float*)d_in[i];
        else if (s == (long long)HID * OUTC)        W2 = (const float*)d_in[i];
        else if (s == OUTC)                         b2 = (const float*)d_in[i];
    }
    if (!x  && n_in > 0) x  = (const float*)d_in[0];
    if (!ei && n_in > 1) ei = (const int*)d_in[1];
    if (!W1 && n_in > 2) W1 = (const float*)d_in[2];
    if (!b1 && n_in > 3) b1 = (const float*)d_in[3];
    if (!W2 && n_in > 4) W2 = (const float*)d_in[4];
    if (!b2 && n_in > 5) b2 = (const float*)d_in[5];

    float* out = (float*)d_out;

    int E  = EDGES_MAX;
    int Nn = out_size / OUTC;
    if (Nn > NODES_MAX) Nn = NODES_MAX;

    const int* src = ei;
    const int* dst = ei + E;

    int nb = (Nn + 255) / 256;
    int eb = (E + 255) / 256;

    k_zero_cnt<<<nb, 256>>>(Nn);
    k_count<<<eb, 256>>>(dst, E, Nn);
    k_scan2<<<1, 1024>>>(Nn);
    k_fill<<<eb, 256>>>(src, dst, E, Nn);

    // layer 1: h1 = x @ W1 via tf32 tensor cores (v2 pipeline)
    {
        dim3 grid(HID / 128, (Nn + 127) / 128);
        k_gemm1_wmma<<<grid, 256>>>(x, W1, Nn, HID, INC);
    }
    k_agg1<<<Nn, HID>>>(b1);

    // layer 2: h2 = g_agg1 @ W2 (SIMT fp32)
    {
        dim3 grid(OUTC / 64, (Nn + 127) / 128);
        k_gemm<128, 64, 8, 8, 4><<<grid, 256>>>(W2, Nn, OUTC, HID);
    }
    k_agg2_lsm<<<Nn, OUTC>>>(b2, out);
}

// round 10
// speedup vs baseline: 1.5800x; 1.1526x over previous
#include <cuda_runtime.h>
#include <math.h>
#include <mma.h>

using namespace nvcuda;

#define NODES_MAX 50000
#define M_PAD 50048          // 391 * 128, wmma epilogue padding
#define HID 256
#define OUTC 64
#define INC 512
#define EDGES_MAX 800000

// ---------------- scratch (static __device__ per allocation rules) ----------
__device__ float g_h1[(size_t)M_PAD * HID];         // x @ W1 (padded rows)
__device__ float g_agg1[(size_t)NODES_MAX * HID];   // relu(norm-agg(h1) + b1)
__device__ float g_h2[(size_t)M_PAD * OUTC];        // agg1 @ W2 (padded rows)
__device__ float g_dinv[NODES_MAX];
__device__ int   g_cnt[NODES_MAX];
__device__ int   g_indptr[NODES_MAX + 1];
__device__ int   g_cursor[NODES_MAX];
__device__ int   g_srcs[EDGES_MAX];

// ---------------- graph preprocessing ---------------------------------------
__global__ void k_zero_cnt(int n) {
    int i = blockIdx.x * blockDim.x + threadIdx.x;
    if (i < n) g_cnt[i] = 0;
}

__global__ void k_count(const int* __restrict__ dst, int E, int n) {
    int i = blockIdx.x * blockDim.x + threadIdx.x;
    if (i < E) {
        int d = dst[i];
        d = max(0, min(n - 1, d));
        atomicAdd(&g_cnt[d], 1);
    }
}

__global__ void __launch_bounds__(1024) k_scan2(int n) {
    const int T = 1024;
    int tid = threadIdx.x;
    int chunk = (n + T - 1) / T;
    int beg = tid * chunk;
    int end = min(beg + chunk, n);

    int sum = 0;
    for (int i = beg; i < end; i++) sum += g_cnt[i];

    int lane = tid & 31, wid = tid >> 5;
    int v = sum;
    #pragma unroll
    for (int off = 1; off < 32; off <<= 1) {
        int t = __shfl_up_sync(0xffffffffu, v, off);
        if (lane >= off) v += t;
    }
    __shared__ int wsum[32];
    if (lane == 31) wsum[wid] = v;
    __syncthreads();
    if (wid == 0) {
        int w = wsum[lane];
        #pragma unroll
        for (int off = 1; off < 32; off <<= 1) {
            int t = __shfl_up_sync(0xffffffffu, w, off);
            if (lane >= off) w += t;
        }
        wsum[lane] = w;
    }
    __syncthreads();
    int excl = v - sum + (wid ? wsum[wid - 1] : 0);

    int run = excl;
    for (int i = beg; i < end; i++) {
        int c = g_cnt[i];
        g_indptr[i] = run;
        g_cursor[i] = run;
        g_dinv[i] = rsqrtf((float)(c + 1));
        run += c;
    }
    if (tid == 0) g_indptr[n] = wsum[31];
}

__global__ void k_fill(const int* __restrict__ src,
                       const int* __restrict__ dst, int E, int n) {
    int i = blockIdx.x * blockDim.x + threadIdx.x;
    if (i < E) {
        int d = dst[i];
        int s = src[i];
        d = max(0, min(n - 1, d));
        s = max(0, min(n - 1, s));
        int p = atomicAdd(&g_cursor[d], 1);
        if (p >= 0 && p < EDGES_MAX) g_srcs[p] = s;
    }
}

// ---------------- GEMM1: tf32 wmma v2, C -> g_h1 ----------------------------
__global__ void __launch_bounds__(256) k_gemm1_wmma(const float* __restrict__ A,
                                                    const float* __restrict__ B,
                                                    int M, int N, int K) {
    const int BM = 128, BN = 128, BK = 32;
    const int LDA = BK + 4;
    const int LDB = BN + 4;
    __shared__ __align__(16) float As[BM][LDA];
    __shared__ __align__(16) float Bs[BK][LDB];

    const int tid = threadIdx.x;
    const int wid = tid >> 5;
    const int warpRow = wid >> 2;
    const int warpCol = wid & 3;
    const int rowBase = blockIdx.y * BM;
    const int colBase = blockIdx.x * BN;

    const int a_r0 = tid >> 3;
    const int a_c  = (tid & 7) * 4;
    const int b_r0 = tid >> 5;
    const int b_c  = (tid & 31) * 4;

    wmma::fragment<wmma::accumulator, 16, 16, 8, float> acc[4][2];
    #pragma unroll
    for (int i = 0; i < 4; i++)
        #pragma unroll
        for (int j = 0; j < 2; j++)
            wmma::fill_fragment(acc[i][j], 0.0f);

    float4 a_pf[4], b_pf[4];

    #pragma unroll
    for (int h = 0; h < 4; h++) {
        int gr = rowBase + a_r0 + h * 32;
        a_pf[h] = make_float4(0.f, 0.f, 0.f, 0.f);
        if (gr < M) a_pf[h] = *reinterpret_cast<const float4*>(&A[(size_t)gr * K + a_c]);
        b_pf[h] = *reinterpret_cast<const float4*>(&B[(size_t)(b_r0 + h * 8) * N + colBase + b_c]);
    }
    #pragma unroll
    for (int h = 0; h < 4; h++) {
        float4 va = a_pf[h];
        va.x = wmma::__float_to_tf32(va.x);  va.y = wmma::__float_to_tf32(va.y);
        va.z = wmma::__float_to_tf32(va.z);  va.w = wmma::__float_to_tf32(va.w);
        *reinterpret_cast<float4*>(&As[a_r0 + h * 32][a_c]) = va;
        float4 vb = b_pf[h];
        vb.x = wmma::__float_to_tf32(vb.x);  vb.y = wmma::__float_to_tf32(vb.y);
        vb.z = wmma::__float_to_tf32(vb.z);  vb.w = wmma::__float_to_tf32(vb.w);
        *reinterpret_cast<float4*>(&Bs[b_r0 + h * 8][b_c]) = vb;
    }
    __syncthreads();

    const int nt = K / BK;
    for (int kt = 0; kt < nt; kt++) {
        if (kt + 1 < nt) {
            int k0 = (kt + 1) * BK;
            #pragma unroll
            for (int h = 0; h < 4; h++) {
                int gr = rowBase + a_r0 + h * 32;
                a_pf[h] = make_float4(0.f, 0.f, 0.f, 0.f);
                if (gr < M)
                    a_pf[h] = *reinterpret_cast<const float4*>(&A[(size_t)gr * K + k0 + a_c]);
                b_pf[h] = *reinterpret_cast<const float4*>(&B[(size_t)(k0 + b_r0 + h * 8) * N + colBase + b_c]);
            }
        }

        #pragma unroll
        for (int k8 = 0; k8 < BK; k8 += 8) {
            wmma::fragment<wmma::matrix_a, 16, 16, 8, wmma::precision::tf32, wmma::row_major> af[4];
            wmma::fragment<wmma::matrix_b, 16, 16, 8, wmma::precision::tf32, wmma::row_major> bf[2];
            #pragma unroll
            for (int i = 0; i < 4; i++)
                wmma::load_matrix_sync(af[i], &As[warpRow * 64 + i * 16][k8], LDA);
            #pragma unroll
            for (int j = 0; j < 2; j++)
                wmma::load_matrix_sync(bf[j], &Bs[k8][warpCol * 32 + j * 16], LDB);
            #pragma unroll
            for (int i = 0; i < 4; i++)
                #pragma unroll
                for (int j = 0; j < 2; j++)
                    wmma::mma_sync(acc[i][j], af[i], bf[j], acc[i][j]);
        }
        __syncthreads();

        if (kt + 1 < nt) {
            #pragma unroll
            for (int h = 0; h < 4; h++) {
                float4 va = a_pf[h];
                va.x = wmma::__float_to_tf32(va.x);  va.y = wmma::__float_to_tf32(va.y);
                va.z = wmma::__float_to_tf32(va.z);  va.w = wmma::__float_to_tf32(va.w);
                *reinterpret_cast<float4*>(&As[a_r0 + h * 32][a_c]) = va;
                float4 vb = b_pf[h];
                vb.x = wmma::__float_to_tf32(vb.x);  vb.y = wmma::__float_to_tf32(vb.y);
                vb.z = wmma::__float_to_tf32(vb.z);  vb.w = wmma::__float_to_tf32(vb.w);
                *reinterpret_cast<float4*>(&Bs[b_r0 + h * 8][b_c]) = vb;
            }
            __syncthreads();
        }
    }

    #pragma unroll
    for (int i = 0; i < 4; i++) {
        int r0 = rowBase + warpRow * 64 + i * 16;
        #pragma unroll
        for (int j = 0; j < 2; j++) {
            int c0 = colBase + warpCol * 32 + j * 16;
            wmma::store_matrix_sync(&g_h1[(size_t)r0 * N + c0], acc[i][j], N,
                                    wmma::mem_row_major);
        }
    }
}

// ---------------- GEMM2: tf32 wmma, g_h2 = g_agg1 @ B (N=64, K=256) ---------
// BM=128, BN=64, BK=32; 8 warps as 4 rows x 2 cols; warp tile 32x32 (2x2 atoms).
__global__ void __launch_bounds__(256) k_gemm2_wmma(const float* __restrict__ B,
                                                    int M) {
    const int BM = 128, BN = 64, BK = 32, K = HID, N = OUTC;
    const int LDA = BK + 4;   // 36
    const int LDB = BN + 4;   // 68
    __shared__ __align__(16) float As[BM][LDA];
    __shared__ __align__(16) float Bs[BK][LDB];

    const float* A = g_agg1;

    const int tid = threadIdx.x;
    const int wid = tid >> 5;
    const int warpRow = wid >> 1;      // 0..3 -> m offset *32
    const int warpCol = wid & 1;       // 0..1 -> n offset *32
    const int rowBase = blockIdx.x * BM;

    const int a_r0 = tid >> 3;         // +32 per pass, 4 passes
    const int a_c  = (tid & 7) * 4;
    const int b_r0 = tid >> 4;         // +16 per pass, 2 passes
    const int b_c  = (tid & 15) * 4;

    wmma::fragment<wmma::accumulator, 16, 16, 8, float> acc[2][2];
    #pragma unroll
    for (int i = 0; i < 2; i++)
        #pragma unroll
        for (int j = 0; j < 2; j++)
            wmma::fill_fragment(acc[i][j], 0.0f);

    float4 a_pf[4], b_pf[2];

    #pragma unroll
    for (int h = 0; h < 4; h++) {
        int gr = rowBase + a_r0 + h * 32;
        a_pf[h] = make_float4(0.f, 0.f, 0.f, 0.f);
        if (gr < M) a_pf[h] = *reinterpret_cast<const float4*>(&A[(size_t)gr * K + a_c]);
    }
    #pragma unroll
    for (int h = 0; h < 2; h++)
        b_pf[h] = *reinterpret_cast<const float4*>(&B[(size_t)(b_r0 + h * 16) * N + b_c]);

    #pragma unroll
    for (int h = 0; h < 4; h++) {
        float4 va = a_pf[h];
        va.x = wmma::__float_to_tf32(va.x);  va.y = wmma::__float_to_tf32(va.y);
        va.z = wmma::__float_to_tf32(va.z);  va.w = wmma::__float_to_tf32(va.w);
        *reinterpret_cast<float4*>(&As[a_r0 + h * 32][a_c]) = va;
    }
    #pragma unroll
    for (int h = 0; h < 2; h++) {
        float4 vb = b_pf[h];
        vb.x = wmma::__float_to_tf32(vb.x);  vb.y = wmma::__float_to_tf32(vb.y);
        vb.z = wmma::__float_to_tf32(vb.z);  vb.w = wmma::__float_to_tf32(vb.w);
        *reinterpret_cast<float4*>(&Bs[b_r0 + h * 16][b_c]) = vb;
    }
    __syncthreads();

    const int nt = K / BK;   // 8
    for (int kt = 0; kt < nt; kt++) {
        if (kt + 1 < nt) {
            int k0 = (kt + 1) * BK;
            #pragma unroll
            for (int h = 0; h < 4; h++) {
                int gr = rowBase + a_r0 + h * 32;
                a_pf[h] = make_float4(0.f, 0.f, 0.f, 0.f);
                if (gr < M)
                    a_pf[h] = *reinterpret_cast<const float4*>(&A[(size_t)gr * K + k0 + a_c]);
            }
            #pragma unroll
            for (int h = 0; h < 2; h++)
                b_pf[h] = *reinterpret_cast<const float4*>(&B[(size_t)(k0 + b_r0 + h * 16) * N + b_c]);
        }

        #pragma unroll
        for (int k8 = 0; k8 < BK; k8 += 8) {
            wmma::fragment<wmma::matrix_a, 16, 16, 8, wmma::precision::tf32, wmma::row_major> af[2];
            wmma::fragment<wmma::matrix_b, 16, 16, 8, wmma::precision::tf32, wmma::row_major> bf[2];
            #pragma unroll
            for (int i = 0; i < 2; i++)
                wmma::load_matrix_sync(af[i], &As[warpRow * 32 + i * 16][k8], LDA);
            #pragma unroll
            for (int j = 0; j < 2; j++)
                wmma::load_matrix_sync(bf[j], &Bs[k8][warpCol * 32 + j * 16], LDB);
            #pragma unroll
            for (int i = 0; i < 2; i++)
                #pragma unroll
                for (int j = 0; j < 2; j++)
                    wmma::mma_sync(acc[i][j], af[i], bf[j], acc[i][j]);
        }
        __syncthreads();

        if (kt + 1 < nt) {
            #pragma unroll
            for (int h = 0; h < 4; h++) {
                float4 va = a_pf[h];
                va.x = wmma::__float_to_tf32(va.x);  va.y = wmma::__float_to_tf32(va.y);
                va.z = wmma::__float_to_tf32(va.z);  va.w = wmma::__float_to_tf32(va.w);
                *reinterpret_cast<float4*>(&As[a_r0 + h * 32][a_c]) = va;
            }
            #pragma unroll
            for (int h = 0; h < 2; h++) {
                float4 vb = b_pf[h];
                vb.x = wmma::__float_to_tf32(vb.x);  vb.y = wmma::__float_to_tf32(vb.y);
                vb.z = wmma::__float_to_tf32(vb.z);  vb.w = wmma::__float_to_tf32(vb.w);
                *reinterpret_cast<float4*>(&Bs[b_r0 + h * 16][b_c]) = vb;
            }
            __syncthreads();
        }
    }

    // epilogue: unguarded (g_h2 rows padded to M_PAD)
    #pragma unroll
    for (int i = 0; i < 2; i++) {
        int r0 = rowBase + warpRow * 32 + i * 16;
        #pragma unroll
        for (int j = 0; j < 2; j++) {
            int c0 = warpCol * 32 + j * 16;
            wmma::store_matrix_sync(&g_h2[(size_t)r0 * N + c0], acc[i][j], N,
                                    wmma::mem_row_major);
        }
    }
}

// ---------------- layer-1 aggregation v2: 4 nodes/block, float4 gathers -----
// 256 threads = 4 groups x 64 lanes; lane l covers features [4l, 4l+4).
// No shared staging, no barriers; g_srcs/g_dinv reads broadcast within group.
__global__ void __launch_bounds__(256) k_agg1(const float* __restrict__ b1, int n) {
    int g = threadIdx.x >> 6;
    int l = threadIdx.x & 63;
    int d = blockIdx.x * 4 + g;
    if (d >= n) return;

    const float4* h1v = reinterpret_cast<const float4*>(g_h1);
    float dd = g_dinv[d];
    float4 self = h1v[(size_t)d * 64 + l];
    float4 acc = make_float4(dd * self.x, dd * self.y, dd * self.z, dd * self.w);

    int beg = g_indptr[d], end = g_indptr[d + 1];
    #pragma unroll 4
    for (int t = beg; t < end; t++) {
        int s = g_srcs[t];
        float w = g_dinv[s];
        float4 v = h1v[(size_t)s * 64 + l];
        acc.x = fmaf(w, v.x, acc.x);
        acc.y = fmaf(w, v.y, acc.y);
        acc.z = fmaf(w, v.z, acc.z);
        acc.w = fmaf(w, v.w, acc.w);
    }

    float4 b = reinterpret_cast<const float4*>(b1)[l];
    float4 o;
    o.x = fmaxf(fmaf(dd, acc.x, b.x), 0.0f);
    o.y = fmaxf(fmaf(dd, acc.y, b.y), 0.0f);
    o.z = fmaxf(fmaf(dd, acc.z, b.z), 0.0f);
    o.w = fmaxf(fmaf(dd, acc.w, b.w), 0.0f);
    reinterpret_cast<float4*>(g_agg1)[(size_t)d * 64 + l] = o;
}

// ---------------- layer-2 aggregation + bias + log_softmax ------------------
__global__ void __launch_bounds__(OUTC) k_agg2_lsm(const float* __restrict__ b2,
                                                   float* __restrict__ out) {
    int d = blockIdx.x;
    int j = threadIdx.x;
    float dd = g_dinv[d];
    float acc = dd * g_h2[(size_t)d * OUTC + j];
    int beg = g_indptr[d], end = g_indptr[d + 1];
    __shared__ int   sh_s[64];
    __shared__ float sh_w[64];
    for (int base = beg; base < end; base += 64) {
        int cnt = min(64, end - base);
        if (j < cnt) {
            int s = g_srcs[base + j];
            sh_s[j] = s;
            sh_w[j] = g_dinv[s];
        }
        __syncthreads();
        #pragma unroll 4
        for (int t = 0; t < cnt; t++)
            acc = fmaf(sh_w[t], g_h2[(size_t)sh_s[t] * OUTC + j], acc);
        __syncthreads();
    }
    float v = dd * acc + b2[j];

    __shared__ float red[2];
    float m = v;
    #pragma unroll
    for (int o = 16; o; o >>= 1) m = fmaxf(m, __shfl_xor_sync(0xffffffffu, m, o));
    if ((j & 31) == 0) red[j >> 5] = m;
    __syncthreads();
    m = fmaxf(red[0], red[1]);
    __syncthreads();
    float e = expf(v - m);
    float s = e;
    #pragma unroll
    for (int o = 16; o; o >>= 1) s += __shfl_xor_sync(0xffffffffu, s, o);
    if ((j & 31) == 0) red[j >> 5] = s;
    __syncthreads();
    float tot = red[0] + red[1];
    out[(size_t)d * OUTC + j] = v - m - logf(tot);
}

// ---------------- entry -----------------------------------------------------
extern "C" void kernel_launch(void* const* d_in, const int* in_sizes, int n_in,
                              void* d_out, int out_size) {
    const float* x  = nullptr;
    const int*   ei = nullptr;
    const float* W1 = nullptr;
    const float* b1 = nullptr;
    const float* W2 = nullptr;
    const float* b2 = nullptr;

    for (int i = 0; i < n_in; i++) {
        long long s = in_sizes[i];
        if      (s == (long long)NODES_MAX * INC)   x  = (const float*)d_in[i];
        else if (s == 2LL * EDGES_MAX)              ei = (const int*)d_in[i];
        else if (s == (long long)INC * HID)         W1 = (const float*)d_in[i];
        else if (s == HID)                          b1 = (const float*)d_in[i];
        else if (s == (long long)HID * OUTC)        W2 = (const float*)d_in[i];
        else if (s == OUTC)                         b2 = (const float*)d_in[i];
    }
    if (!x  && n_in > 0) x  = (const float*)d_in[0];
    if (!ei && n_in > 1) ei = (const int*)d_in[1];
    if (!W1 && n_in > 2) W1 = (const float*)d_in[2];
    if (!b1 && n_in > 3) b1 = (const float*)d_in[3];
    if (!W2 && n_in > 4) W2 = (const float*)d_in[4];
    if (!b2 && n_in > 5) b2 = (const float*)d_in[5];

    float* out = (float*)d_out;

    int E  = EDGES_MAX;
    int Nn = out_size / OUTC;
    if (Nn > NODES_MAX) Nn = NODES_MAX;

    const int* src = ei;
    const int* dst = ei + E;

    int nb = (Nn + 255) / 256;
    int eb = (E + 255) / 256;

    k_zero_cnt<<<nb, 256>>>(Nn);
    k_count<<<eb, 256>>>(dst, E, Nn);
    k_scan2<<<1, 1024>>>(Nn);
    k_fill<<<eb, 256>>>(src, dst, E, Nn);

    // layer 1: h1 = x @ W1 (tf32 wmma v2)
    {
        dim3 grid(HID / 128, (Nn + 127) / 128);
        k_gemm1_wmma<<<grid, 256>>>(x, W1, Nn, HID, INC);
    }
    k_agg1<<<(Nn + 3) / 4, 256>>>(b1, Nn);

    // layer 2: h2 = g_agg1 @ W2 (tf32 wmma)
    k_gemm2_wmma<<<(Nn + 127) / 128, 256>>>(W2, Nn);
    k_agg2_lsm<<<Nn, OUTC>>>(b2, out);
}

// round 11
// speedup vs baseline: 1.6095x; 1.0186x over previous
#include <cuda_runtime.h>
#include <math.h>
#include <mma.h>

using namespace nvcuda;

#define NODES_MAX 50000
#define M_PAD 50048          // 391 * 128, wmma epilogue padding
#define HID 256
#define OUTC 64
#define INC 512
#define EDGES_MAX 800000

// ---------------- scratch (static __device__ per allocation rules) ----------
__device__ float g_h1[(size_t)M_PAD * HID];         // x @ W1 (padded rows)
__device__ float g_agg1[(size_t)NODES_MAX * HID];   // relu(norm-agg(h1) + b1)
__device__ float g_h2[(size_t)M_PAD * OUTC];        // agg1 @ W2 (padded rows)
__device__ float g_dinv[NODES_MAX];
__device__ int   g_cnt[NODES_MAX];
__device__ int   g_indptr[NODES_MAX + 1];
__device__ int   g_cursor[NODES_MAX];
__device__ int   g_srcs[EDGES_MAX];
__device__ float g_wsrc[EDGES_MAX];                 // dinv[src] per CSR slot

// ---------------- graph preprocessing ---------------------------------------
__global__ void k_zero_cnt(int n) {
    int i = blockIdx.x * blockDim.x + threadIdx.x;
    if (i < n) g_cnt[i] = 0;
}

__global__ void k_count(const int* __restrict__ dst, int E, int n) {
    int i = blockIdx.x * blockDim.x + threadIdx.x;
    if (i < E) {
        int d = dst[i];
        d = max(0, min(n - 1, d));
        atomicAdd(&g_cnt[d], 1);
    }
}

__global__ void __launch_bounds__(1024) k_scan2(int n) {
    const int T = 1024;
    int tid = threadIdx.x;
    int chunk = (n + T - 1) / T;
    int beg = tid * chunk;
    int end = min(beg + chunk, n);

    int sum = 0;
    for (int i = beg; i < end; i++) sum += g_cnt[i];

    int lane = tid & 31, wid = tid >> 5;
    int v = sum;
    #pragma unroll
    for (int off = 1; off < 32; off <<= 1) {
        int t = __shfl_up_sync(0xffffffffu, v, off);
        if (lane >= off) v += t;
    }
    __shared__ int wsum[32];
    if (lane == 31) wsum[wid] = v;
    __syncthreads();
    if (wid == 0) {
        int w = wsum[lane];
        #pragma unroll
        for (int off = 1; off < 32; off <<= 1) {
            int t = __shfl_up_sync(0xffffffffu, w, off);
            if (lane >= off) w += t;
        }
        wsum[lane] = w;
    }
    __syncthreads();
    int excl = v - sum + (wid ? wsum[wid - 1] : 0);

    int run = excl;
    for (int i = beg; i < end; i++) {
        int c = g_cnt[i];
        g_indptr[i] = run;
        g_cursor[i] = run;
        g_dinv[i] = rsqrtf((float)(c + 1));
        run += c;
    }
    if (tid == 0) g_indptr[n] = wsum[31];
}

// fill CSR; also store w = dinv[src] (dinv is final: scan2 ran before this)
__global__ void k_fill(const int* __restrict__ src,
                       const int* __restrict__ dst, int E, int n) {
    int i = blockIdx.x * blockDim.x + threadIdx.x;
    if (i < E) {
        int d = dst[i];
        int s = src[i];
        d = max(0, min(n - 1, d));
        s = max(0, min(n - 1, s));
        int p = atomicAdd(&g_cursor[d], 1);
        if (p >= 0 && p < EDGES_MAX) {
            g_srcs[p] = s;
            g_wsrc[p] = g_dinv[s];
        }
    }
}

// ---------------- GEMM1: tf32 wmma v2, C -> g_h1 ----------------------------
__global__ void __launch_bounds__(256) k_gemm1_wmma(const float* __restrict__ A,
                                                    const float* __restrict__ B,
                                                    int M, int N, int K) {
    const int BM = 128, BN = 128, BK = 32;
    const int LDA = BK + 4;
    const int LDB = BN + 4;
    __shared__ __align__(16) float As[BM][LDA];
    __shared__ __align__(16) float Bs[BK][LDB];

    const int tid = threadIdx.x;
    const int wid = tid >> 5;
    const int warpRow = wid >> 2;
    const int warpCol = wid & 3;
    const int rowBase = blockIdx.y * BM;
    const int colBase = blockIdx.x * BN;

    const int a_r0 = tid >> 3;
    const int a_c  = (tid & 7) * 4;
    const int b_r0 = tid >> 5;
    const int b_c  = (tid & 31) * 4;

    wmma::fragment<wmma::accumulator, 16, 16, 8, float> acc[4][2];
    #pragma unroll
    for (int i = 0; i < 4; i++)
        #pragma unroll
        for (int j = 0; j < 2; j++)
            wmma::fill_fragment(acc[i][j], 0.0f);

    float4 a_pf[4], b_pf[4];

    #pragma unroll
    for (int h = 0; h < 4; h++) {
        int gr = rowBase + a_r0 + h * 32;
        a_pf[h] = make_float4(0.f, 0.f, 0.f, 0.f);
        if (gr < M) a_pf[h] = *reinterpret_cast<const float4*>(&A[(size_t)gr * K + a_c]);
        b_pf[h] = *reinterpret_cast<const float4*>(&B[(size_t)(b_r0 + h * 8) * N + colBase + b_c]);
    }
    #pragma unroll
    for (int h = 0; h < 4; h++) {
        float4 va = a_pf[h];
        va.x = wmma::__float_to_tf32(va.x);  va.y = wmma::__float_to_tf32(va.y);
        va.z = wmma::__float_to_tf32(va.z);  va.w = wmma::__float_to_tf32(va.w);
        *reinterpret_cast<float4*>(&As[a_r0 + h * 32][a_c]) = va;
        float4 vb = b_pf[h];
        vb.x = wmma::__float_to_tf32(vb.x);  vb.y = wmma::__float_to_tf32(vb.y);
        vb.z = wmma::__float_to_tf32(vb.z);  vb.w = wmma::__float_to_tf32(vb.w);
        *reinterpret_cast<float4*>(&Bs[b_r0 + h * 8][b_c]) = vb;
    }
    __syncthreads();

    const int nt = K / BK;
    for (int kt = 0; kt < nt; kt++) {
        if (kt + 1 < nt) {
            int k0 = (kt + 1) * BK;
            #pragma unroll
            for (int h = 0; h < 4; h++) {
                int gr = rowBase + a_r0 + h * 32;
                a_pf[h] = make_float4(0.f, 0.f, 0.f, 0.f);
                if (gr < M)
                    a_pf[h] = *reinterpret_cast<const float4*>(&A[(size_t)gr * K + k0 + a_c]);
                b_pf[h] = *reinterpret_cast<const float4*>(&B[(size_t)(k0 + b_r0 + h * 8) * N + colBase + b_c]);
            }
        }

        #pragma unroll
        for (int k8 = 0; k8 < BK; k8 += 8) {
            wmma::fragment<wmma::matrix_a, 16, 16, 8, wmma::precision::tf32, wmma::row_major> af[4];
            wmma::fragment<wmma::matrix_b, 16, 16, 8, wmma::precision::tf32, wmma::row_major> bf[2];
            #pragma unroll
            for (int i = 0; i < 4; i++)
                wmma::load_matrix_sync(af[i], &As[warpRow * 64 + i * 16][k8], LDA);
            #pragma unroll
            for (int j = 0; j < 2; j++)
                wmma::load_matrix_sync(bf[j], &Bs[k8][warpCol * 32 + j * 16], LDB);
            #pragma unroll
            for (int i = 0; i < 4; i++)
                #pragma unroll
                for (int j = 0; j < 2; j++)
                    wmma::mma_sync(acc[i][j], af[i], bf[j], acc[i][j]);
        }
        __syncthreads();

        if (kt + 1 < nt) {
            #pragma unroll
            for (int h = 0; h < 4; h++) {
                float4 va = a_pf[h];
                va.x = wmma::__float_to_tf32(va.x);  va.y = wmma::__float_to_tf32(va.y);
                va.z = wmma::__float_to_tf32(va.z);  va.w = wmma::__float_to_tf32(va.w);
                *reinterpret_cast<float4*>(&As[a_r0 + h * 32][a_c]) = va;
                float4 vb = b_pf[h];
                vb.x = wmma::__float_to_tf32(vb.x);  vb.y = wmma::__float_to_tf32(vb.y);
                vb.z = wmma::__float_to_tf32(vb.z);  vb.w = wmma::__float_to_tf32(vb.w);
                *reinterpret_cast<float4*>(&Bs[b_r0 + h * 8][b_c]) = vb;
            }
            __syncthreads();
        }
    }

    #pragma unroll
    for (int i = 0; i < 4; i++) {
        int r0 = rowBase + warpRow * 64 + i * 16;
        #pragma unroll
        for (int j = 0; j < 2; j++) {
            int c0 = colBase + warpCol * 32 + j * 16;
            wmma::store_matrix_sync(&g_h1[(size_t)r0 * N + c0], acc[i][j], N,
                                    wmma::mem_row_major);
        }
    }
}

// ---------------- GEMM2: tf32 wmma, g_h2 = g_agg1 @ B (N=64, K=256) ---------
__global__ void __launch_bounds__(256) k_gemm2_wmma(const float* __restrict__ B,
                                                    int M) {
    const int BM = 128, BN = 64, BK = 32, K = HID, N = OUTC;
    const int LDA = BK + 4;
    const int LDB = BN + 4;
    __shared__ __align__(16) float As[BM][LDA];
    __shared__ __align__(16) float Bs[BK][LDB];

    const float* A = g_agg1;

    const int tid = threadIdx.x;
    const int wid = tid >> 5;
    const int warpRow = wid >> 1;
    const int warpCol = wid & 1;
    const int rowBase = blockIdx.x * BM;

    const int a_r0 = tid >> 3;
    const int a_c  = (tid & 7) * 4;
    const int b_r0 = tid >> 4;
    const int b_c  = (tid & 15) * 4;

    wmma::fragment<wmma::accumulator, 16, 16, 8, float> acc[2][2];
    #pragma unroll
    for (int i = 0; i < 2; i++)
        #pragma unroll
        for (int j = 0; j < 2; j++)
            wmma::fill_fragment(acc[i][j], 0.0f);

    float4 a_pf[4], b_pf[2];

    #pragma unroll
    for (int h = 0; h < 4; h++) {
        int gr = rowBase + a_r0 + h * 32;
        a_pf[h] = make_float4(0.f, 0.f, 0.f, 0.f);
        if (gr < M) a_pf[h] = *reinterpret_cast<const float4*>(&A[(size_t)gr * K + a_c]);
    }
    #pragma unroll
    for (int h = 0; h < 2; h++)
        b_pf[h] = *reinterpret_cast<const float4*>(&B[(size_t)(b_r0 + h * 16) * N + b_c]);

    #pragma unroll
    for (int h = 0; h < 4; h++) {
        float4 va = a_pf[h];
        va.x = wmma::__float_to_tf32(va.x);  va.y = wmma::__float_to_tf32(va.y);
        va.z = wmma::__float_to_tf32(va.z);  va.w = wmma::__float_to_tf32(va.w);
        *reinterpret_cast<float4*>(&As[a_r0 + h * 32][a_c]) = va;
    }
    #pragma unroll
    for (int h = 0; h < 2; h++) {
        float4 vb = b_pf[h];
        vb.x = wmma::__float_to_tf32(vb.x);  vb.y = wmma::__float_to_tf32(vb.y);
        vb.z = wmma::__float_to_tf32(vb.z);  vb.w = wmma::__float_to_tf32(vb.w);
        *reinterpret_cast<float4*>(&Bs[b_r0 + h * 16][b_c]) = vb;
    }
    __syncthreads();

    const int nt = K / BK;
    for (int kt = 0; kt < nt; kt++) {
        if (kt + 1 < nt) {
            int k0 = (kt + 1) * BK;
            #pragma unroll
            for (int h = 0; h < 4; h++) {
                int gr = rowBase + a_r0 + h * 32;
                a_pf[h] = make_float4(0.f, 0.f, 0.f, 0.f);
                if (gr < M)
                    a_pf[h] = *reinterpret_cast<const float4*>(&A[(size_t)gr * K + k0 + a_c]);
            }
            #pragma unroll
            for (int h = 0; h < 2; h++)
                b_pf[h] = *reinterpret_cast<const float4*>(&B[(size_t)(k0 + b_r0 + h * 16) * N + b_c]);
        }

        #pragma unroll
        for (int k8 = 0; k8 < BK; k8 += 8) {
            wmma::fragment<wmma::matrix_a, 16, 16, 8, wmma::precision::tf32, wmma::row_major> af[2];
            wmma::fragment<wmma::matrix_b, 16, 16, 8, wmma::precision::tf32, wmma::row_major> bf[2];
            #pragma unroll
            for (int i = 0; i < 2; i++)
                wmma::load_matrix_sync(af[i], &As[warpRow * 32 + i * 16][k8], LDA);
            #pragma unroll
            for (int j = 0; j < 2; j++)
                wmma::load_matrix_sync(bf[j], &Bs[k8][warpCol * 32 + j * 16], LDB);
            #pragma unroll
            for (int i = 0; i < 2; i++)
                #pragma unroll
                for (int j = 0; j < 2; j++)
                    wmma::mma_sync(acc[i][j], af[i], bf[j], acc[i][j]);
        }
        __syncthreads();

        if (kt + 1 < nt) {
            #pragma unroll
            for (int h = 0; h < 4; h++) {
                float4 va = a_pf[h];
                va.x = wmma::__float_to_tf32(va.x);  va.y = wmma::__float_to_tf32(va.y);
                va.z = wmma::__float_to_tf32(va.z);  va.w = wmma::__float_to_tf32(va.w);
                *reinterpret_cast<float4*>(&As[a_r0 + h * 32][a_c]) = va;
            }
            #pragma unroll
            for (int h = 0; h < 2; h++) {
                float4 vb = b_pf[h];
                vb.x = wmma::__float_to_tf32(vb.x);  vb.y = wmma::__float_to_tf32(vb.y);
                vb.z = wmma::__float_to_tf32(vb.z);  vb.w = wmma::__float_to_tf32(vb.w);
                *reinterpret_cast<float4*>(&Bs[b_r0 + h * 16][b_c]) = vb;
            }
            __syncthreads();
        }
    }

    #pragma unroll
    for (int i = 0; i < 2; i++) {
        int r0 = rowBase + warpRow * 32 + i * 16;
        #pragma unroll
        for (int j = 0; j < 2; j++) {
            int c0 = warpCol * 32 + j * 16;
            wmma::store_matrix_sync(&g_h2[(size_t)r0 * N + c0], acc[i][j], N,
                                    wmma::mem_row_major);
        }
    }
}

// ---------------- layer-1 aggregation: 4 nodes/block, float4, parallel w ----
__global__ void __launch_bounds__(256) k_agg1(const float* __restrict__ b1, int n) {
    int g = threadIdx.x >> 6;
    int l = threadIdx.x & 63;
    int d = blockIdx.x * 4 + g;
    if (d >= n) return;

    const float4* h1v = reinterpret_cast<const float4*>(g_h1);
    float dd = g_dinv[d];
    float4 self = h1v[(size_t)d * 64 + l];
    float4 acc = make_float4(dd * self.x, dd * self.y, dd * self.z, dd * self.w);

    int beg = g_indptr[d], end = g_indptr[d + 1];
    #pragma unroll 4
    for (int t = beg; t < end; t++) {
        int s = g_srcs[t];
        float w = g_wsrc[t];          // parallel load — no s->dinv dependency
        float4 v = h1v[(size_t)s * 64 + l];
        acc.x = fmaf(w, v.x, acc.x);
        acc.y = fmaf(w, v.y, acc.y);
        acc.z = fmaf(w, v.z, acc.z);
        acc.w = fmaf(w, v.w, acc.w);
    }

    float4 b = reinterpret_cast<const float4*>(b1)[l];
    float4 o;
    o.x = fmaxf(fmaf(dd, acc.x, b.x), 0.0f);
    o.y = fmaxf(fmaf(dd, acc.y, b.y), 0.0f);
    o.z = fmaxf(fmaf(dd, acc.z, b.z), 0.0f);
    o.w = fmaxf(fmaf(dd, acc.w, b.w), 0.0f);
    reinterpret_cast<float4*>(g_agg1)[(size_t)d * 64 + l] = o;
}

// ---------------- layer-2 agg + bias + log_softmax v2: barrier-free ---------
// 256 threads = 16 nodes x 16 lanes; lane l covers features [4l, 4l+4).
// log_softmax reduced with shfl_xor inside the aligned 16-lane group.
__global__ void __launch_bounds__(256) k_agg2_lsm(const float* __restrict__ b2,
                                                  float* __restrict__ out, int n) {
    int g = threadIdx.x >> 4;
    int l = threadIdx.x & 15;
    int d = blockIdx.x * 16 + g;
    if (d >= n) return;

    const float4* h2v = reinterpret_cast<const float4*>(g_h2);
    float dd = g_dinv[d];
    float4 self = h2v[(size_t)d * 16 + l];
    float4 acc = make_float4(dd * self.x, dd * self.y, dd * self.z, dd * self.w);

    int beg = g_indptr[d], end = g_indptr[d + 1];
    #pragma unroll 4
    for (int t = beg; t < end; t++) {
        int s = g_srcs[t];
        float w = g_wsrc[t];
        float4 v = h2v[(size_t)s * 16 + l];
        acc.x = fmaf(w, v.x, acc.x);
        acc.y = fmaf(w, v.y, acc.y);
        acc.z = fmaf(w, v.z, acc.z);
        acc.w = fmaf(w, v.w, acc.w);
    }

    float4 b = reinterpret_cast<const float4*>(b2)[l];
    float4 v4;
    v4.x = fmaf(dd, acc.x, b.x);
    v4.y = fmaf(dd, acc.y, b.y);
    v4.z = fmaf(dd, acc.z, b.z);
    v4.w = fmaf(dd, acc.w, b.w);

    // max over 64 features: intra-float4 then 16-lane shfl tree
    float m = fmaxf(fmaxf(v4.x, v4.y), fmaxf(v4.z, v4.w));
    #pragma unroll
    for (int o = 8; o; o >>= 1) m = fmaxf(m, __shfl_xor_sync(0xffffffffu, m, o));
    // sum of exp
    float s = expf(v4.x - m) + expf(v4.y - m) + expf(v4.z - m) + expf(v4.w - m);
    #pragma unroll
    for (int o = 8; o; o >>= 1) s += __shfl_xor_sync(0xffffffffu, s, o);
    float lse = m + logf(s);

    float4 o4;
    o4.x = v4.x - lse;  o4.y = v4.y - lse;
    o4.z = v4.z - lse;  o4.w = v4.w - lse;
    reinterpret_cast<float4*>(out)[(size_t)d * 16 + l] = o4;
}

// ---------------- entry -----------------------------------------------------
extern "C" void kernel_launch(void* const* d_in, const int* in_sizes, int n_in,
                              void* d_out, int out_size) {
    const float* x  = nullptr;
    const int*   ei = nullptr;
    const float* W1 = nullptr;
    const float* b1 = nullptr;
    const float* W2 = nullptr;
    const float* b2 = nullptr;

    for (int i = 0; i < n_in; i++) {
        long long s = in_sizes[i];
        if      (s == (long long)NODES_MAX * INC)   x  = (const float*)d_in[i];
        else if (s == 2LL * EDGES_MAX)              ei = (const int*)d_in[i];
        else if (s == (long long)INC * HID)         W1 = (const float*)d_in[i];
        else if (s == HID)                          b1 = (const float*)d_in[i];
        else if (s == (long long)HID * OUTC)        W2 = (const float*)d_in[i];
        else if (s == OUTC)                         b2 = (const float*)d_in[i];
    }
    if (!x  && n_in > 0) x  = (const float*)d_in[0];
    if (!ei && n_in > 1) ei = (const int*)d_in[1];
    if (!W1 && n_in > 2) W1 = (const float*)d_in[2];
    if (!b1 && n_in > 3) b1 = (const float*)d_in[3];
    if (!W2 && n_in > 4) W2 = (const float*)d_in[4];
    if (!b2 && n_in > 5) b2 = (const float*)d_in[5];

    float* out = (float*)d_out;

    int E  = EDGES_MAX;
    int Nn = out_size / OUTC;
    if (Nn > NODES_MAX) Nn = NODES_MAX;

    const int* src = ei;
    const int* dst = ei + E;

    int nb = (Nn + 255) / 256;
    int eb = (E + 255) / 256;

    k_zero_cnt<<<nb, 256>>>(Nn);
    k_count<<<eb, 256>>>(dst, E, Nn);
    k_scan2<<<1, 1024>>>(Nn);
    k_fill<<<eb, 256>>>(src, dst, E, Nn);

    // layer 1: h1 = x @ W1 (tf32 wmma v2)
    {
        dim3 grid(HID / 128, (Nn + 127) / 128);
        k_gemm1_wmma<<<grid, 256>>>(x, W1, Nn, HID, INC);
    }
    k_agg1<<<(Nn + 3) / 4, 256>>>(b1, Nn);

    // layer 2: h2 = g_agg1 @ W2 (tf32 wmma) + fused agg/lsm
    k_gemm2_wmma<<<(Nn + 127) / 128, 256>>>(W2, Nn);
    k_agg2_lsm<<<(Nn + 15) / 16, 256>>>(b2, out, Nn);
}

// round 12
// speedup vs baseline: 1.6220x; 1.0078x over previous
#include <cuda_runtime.h>
#include <math.h>
#include <mma.h>

using namespace nvcuda;

#define NODES_MAX 50000
#define M_PAD 50048          // 391 * 128, wmma epilogue padding
#define HID 256
#define OUTC 64
#define INC 512
#define EDGES_MAX 800000

// ---------------- scratch (static __device__ per allocation rules) ----------
__device__ float g_h1[(size_t)M_PAD * HID];         // x @ W1 (padded rows)
__device__ float g_agg1[(size_t)NODES_MAX * HID];   // relu(norm-agg(h1) + b1)
__device__ float g_h2[(size_t)M_PAD * OUTC];        // agg1 @ W2 (padded rows)
__device__ float g_dinv[NODES_MAX];
__device__ int   g_cnt[NODES_MAX];
__device__ int   g_indptr[NODES_MAX + 1];
__device__ int   g_cursor[NODES_MAX];
__device__ int   g_srcs[EDGES_MAX];
__device__ float g_wsrc[EDGES_MAX];                 // dinv[src] per CSR slot

// ---------------- graph preprocessing ---------------------------------------
__global__ void k_zero_cnt(int n) {
    int i = blockIdx.x * blockDim.x + threadIdx.x;
    if (i < n) g_cnt[i] = 0;
}

__global__ void k_count(const int* __restrict__ dst, int E, int n) {
    int i = blockIdx.x * blockDim.x + threadIdx.x;
    if (i < E) {
        int d = dst[i];
        d = max(0, min(n - 1, d));
        atomicAdd(&g_cnt[d], 1);
    }
}

__global__ void __launch_bounds__(1024) k_scan2(int n) {
    const int T = 1024;
    int tid = threadIdx.x;
    int chunk = (n + T - 1) / T;
    int beg = tid * chunk;
    int end = min(beg + chunk, n);

    int sum = 0;
    for (int i = beg; i < end; i++) sum += g_cnt[i];

    int lane = tid & 31, wid = tid >> 5;
    int v = sum;
    #pragma unroll
    for (int off = 1; off < 32; off <<= 1) {
        int t = __shfl_up_sync(0xffffffffu, v, off);
        if (lane >= off) v += t;
    }
    __shared__ int wsum[32];
    if (lane == 31) wsum[wid] = v;
    __syncthreads();
    if (wid == 0) {
        int w = wsum[lane];
        #pragma unroll
        for (int off = 1; off < 32; off <<= 1) {
            int t = __shfl_up_sync(0xffffffffu, w, off);
            if (lane >= off) w += t;
        }
        wsum[lane] = w;
    }
    __syncthreads();
    int excl = v - sum + (wid ? wsum[wid - 1] : 0);

    int run = excl;
    for (int i = beg; i < end; i++) {
        int c = g_cnt[i];
        g_indptr[i] = run;
        g_cursor[i] = run;
        g_dinv[i] = rsqrtf((float)(c + 1));
        run += c;
    }
    if (tid == 0) g_indptr[n] = wsum[31];
}

__global__ void k_fill(const int* __restrict__ src,
                       const int* __restrict__ dst, int E, int n) {
    int i = blockIdx.x * blockDim.x + threadIdx.x;
    if (i < E) {
        int d = dst[i];
        int s = src[i];
        d = max(0, min(n - 1, d));
        s = max(0, min(n - 1, s));
        int p = atomicAdd(&g_cursor[d], 1);
        if (p >= 0 && p < EDGES_MAX) {
            g_srcs[p] = s;
            g_wsrc[p] = g_dinv[s];
        }
    }
}

// ---------------- GEMM1: tf32 wmma v3 (double-buffered smem) ----------------
// BM=128, BN=128, BK=32; dyn smem = 2*(128*36 + 32*132)*4 = 70656 B.
// One __syncthreads per K-tile (16 total); staging overlaps MMA.
#define G1_LDA 36
#define G1_LDB 132
#define G1_ASZ (128 * G1_LDA)
#define G1_BSZ (32 * G1_LDB)
#define G1_BUF (G1_ASZ + G1_BSZ)
#define G1_SMEM (2 * G1_BUF * 4)

__global__ void __launch_bounds__(256) k_gemm1_wmma(const float* __restrict__ A,
                                                    const float* __restrict__ B,
                                                    int M, int N, int K) {
    const int BM = 128, BK = 32;
    extern __shared__ __align__(16) float dyn[];

    const int tid = threadIdx.x;
    const int wid = tid >> 5;
    const int warpRow = wid >> 2;      // 0..1 -> m*64
    const int warpCol = wid & 3;       // 0..3 -> n*32
    const int rowBase = blockIdx.y * BM;
    const int colBase = blockIdx.x * 128;

    const int a_r0 = tid >> 3;
    const int a_c  = (tid & 7) * 4;
    const int b_r0 = tid >> 5;
    const int b_c  = (tid & 31) * 4;

    wmma::fragment<wmma::accumulator, 16, 16, 8, float> acc[4][2];
    #pragma unroll
    for (int i = 0; i < 4; i++)
        #pragma unroll
        for (int j = 0; j < 2; j++)
            wmma::fill_fragment(acc[i][j], 0.0f);

    float4 a_pf[4], b_pf[4];

    // load + stage tile 0 into buffer 0
    #pragma unroll
    for (int h = 0; h < 4; h++) {
        int gr = rowBase + a_r0 + h * 32;
        a_pf[h] = make_float4(0.f, 0.f, 0.f, 0.f);
        if (gr < M) a_pf[h] = *reinterpret_cast<const float4*>(&A[(size_t)gr * K + a_c]);
        b_pf[h] = *reinterpret_cast<const float4*>(&B[(size_t)(b_r0 + h * 8) * N + colBase + b_c]);
    }
    {
        float* As = dyn;
        float* Bs = dyn + G1_ASZ;
        #pragma unroll
        for (int h = 0; h < 4; h++) {
            float4 va = a_pf[h];
            va.x = wmma::__float_to_tf32(va.x);  va.y = wmma::__float_to_tf32(va.y);
            va.z = wmma::__float_to_tf32(va.z);  va.w = wmma::__float_to_tf32(va.w);
            *reinterpret_cast<float4*>(&As[(a_r0 + h * 32) * G1_LDA + a_c]) = va;
            float4 vb = b_pf[h];
            vb.x = wmma::__float_to_tf32(vb.x);  vb.y = wmma::__float_to_tf32(vb.y);
            vb.z = wmma::__float_to_tf32(vb.z);  vb.w = wmma::__float_to_tf32(vb.w);
            *reinterpret_cast<float4*>(&Bs[(b_r0 + h * 8) * G1_LDB + b_c]) = vb;
        }
    }
    __syncthreads();

    const int nt = K / BK;   // 16
    for (int kt = 0; kt < nt; kt++) {
        const int cur = kt & 1;
        float* As = dyn + cur * G1_BUF;
        float* Bs = dyn + cur * G1_BUF + G1_ASZ;

        // prefetch next tile into regs (overlaps MMA)
        if (kt + 1 < nt) {
            int k0 = (kt + 1) * BK;
            #pragma unroll
            for (int h = 0; h < 4; h++) {
                int gr = rowBase + a_r0 + h * 32;
                a_pf[h] = make_float4(0.f, 0.f, 0.f, 0.f);
                if (gr < M)
                    a_pf[h] = *reinterpret_cast<const float4*>(&A[(size_t)gr * K + k0 + a_c]);
                b_pf[h] = *reinterpret_cast<const float4*>(&B[(size_t)(k0 + b_r0 + h * 8) * N + colBase + b_c]);
            }
        }

        #pragma unroll
        for (int k8 = 0; k8 < BK; k8 += 8) {
            wmma::fragment<wmma::matrix_a, 16, 16, 8, wmma::precision::tf32, wmma::row_major> af[4];
            wmma::fragment<wmma::matrix_b, 16, 16, 8, wmma::precision::tf32, wmma::row_major> bf[2];
            #pragma unroll
            for (int i = 0; i < 4; i++)
                wmma::load_matrix_sync(af[i], &As[(warpRow * 64 + i * 16) * G1_LDA + k8], G1_LDA);
            #pragma unroll
            for (int j = 0; j < 2; j++)
                wmma::load_matrix_sync(bf[j], &Bs[k8 * G1_LDB + warpCol * 32 + j * 16], G1_LDB);
            #pragma unroll
            for (int i = 0; i < 4; i++)
                #pragma unroll
                for (int j = 0; j < 2; j++)
                    wmma::mma_sync(acc[i][j], af[i], bf[j], acc[i][j]);
        }

        // stage next tile into the alternate buffer (safe: last read 2 iters ago)
        if (kt + 1 < nt) {
            float* Asn = dyn + (cur ^ 1) * G1_BUF;
            float* Bsn = dyn + (cur ^ 1) * G1_BUF + G1_ASZ;
            #pragma unroll
            for (int h = 0; h < 4; h++) {
                float4 va = a_pf[h];
                va.x = wmma::__float_to_tf32(va.x);  va.y = wmma::__float_to_tf32(va.y);
                va.z = wmma::__float_to_tf32(va.z);  va.w = wmma::__float_to_tf32(va.w);
                *reinterpret_cast<float4*>(&Asn[(a_r0 + h * 32) * G1_LDA + a_c]) = va;
                float4 vb = b_pf[h];
                vb.x = wmma::__float_to_tf32(vb.x);  vb.y = wmma::__float_to_tf32(vb.y);
                vb.z = wmma::__float_to_tf32(vb.z);  vb.w = wmma::__float_to_tf32(vb.w);
                *reinterpret_cast<float4*>(&Bsn[(b_r0 + h * 8) * G1_LDB + b_c]) = vb;
            }
        }
        __syncthreads();
    }

    #pragma unroll
    for (int i = 0; i < 4; i++) {
        int r0 = rowBase + warpRow * 64 + i * 16;
        #pragma unroll
        for (int j = 0; j < 2; j++) {
            int c0 = colBase + warpCol * 32 + j * 16;
            wmma::store_matrix_sync(&g_h1[(size_t)r0 * N + c0], acc[i][j], N,
                                    wmma::mem_row_major);
        }
    }
}

// ---------------- GEMM2: tf32 wmma (double-buffered), g_h2 = g_agg1 @ B -----
#define G2_LDA 36
#define G2_LDB 68
#define G2_ASZ (128 * G2_LDA)
#define G2_BSZ (32 * G2_LDB)
#define G2_BUF (G2_ASZ + G2_BSZ)
#define G2_SMEM (2 * G2_BUF * 4)

__global__ void __launch_bounds__(256) k_gemm2_wmma(const float* __restrict__ B,
                                                    int M) {
    const int BM = 128, BK = 32, K = HID, N = OUTC;
    extern __shared__ __align__(16) float dyn[];

    const float* A = g_agg1;

    const int tid = threadIdx.x;
    const int wid = tid >> 5;
    const int warpRow = wid >> 1;      // 0..3 -> m*32
    const int warpCol = wid & 1;       // 0..1 -> n*32
    const int rowBase = blockIdx.x * BM;

    const int a_r0 = tid >> 3;
    const int a_c  = (tid & 7) * 4;
    const int b_r0 = tid >> 4;
    const int b_c  = (tid & 15) * 4;

    wmma::fragment<wmma::accumulator, 16, 16, 8, float> acc[2][2];
    #pragma unroll
    for (int i = 0; i < 2; i++)
        #pragma unroll
        for (int j = 0; j < 2; j++)
            wmma::fill_fragment(acc[i][j], 0.0f);

    float4 a_pf[4], b_pf[2];

    #pragma unroll
    for (int h = 0; h < 4; h++) {
        int gr = rowBase + a_r0 + h * 32;
        a_pf[h] = make_float4(0.f, 0.f, 0.f, 0.f);
        if (gr < M) a_pf[h] = *reinterpret_cast<const float4*>(&A[(size_t)gr * K + a_c]);
    }
    #pragma unroll
    for (int h = 0; h < 2; h++)
        b_pf[h] = *reinterpret_cast<const float4*>(&B[(size_t)(b_r0 + h * 16) * N + b_c]);

    {
        float* As = dyn;
        float* Bs = dyn + G2_ASZ;
        #pragma unroll
        for (int h = 0; h < 4; h++) {
            float4 va = a_pf[h];
            va.x = wmma::__float_to_tf32(va.x);  va.y = wmma::__float_to_tf32(va.y);
            va.z = wmma::__float_to_tf32(va.z);  va.w = wmma::__float_to_tf32(va.w);
            *reinterpret_cast<float4*>(&As[(a_r0 + h * 32) * G2_LDA + a_c]) = va;
        }
        #pragma unroll
        for (int h = 0; h < 2; h++) {
            float4 vb = b_pf[h];
            vb.x = wmma::__float_to_tf32(vb.x);  vb.y = wmma::__float_to_tf32(vb.y);
            vb.z = wmma::__float_to_tf32(vb.z);  vb.w = wmma::__float_to_tf32(vb.w);
            *reinterpret_cast<float4*>(&Bs[(b_r0 + h * 16) * G2_LDB + b_c]) = vb;
        }
    }
    __syncthreads();

    const int nt = K / BK;   // 8
    for (int kt = 0; kt < nt; kt++) {
        const int cur = kt & 1;
        float* As = dyn + cur * G2_BUF;
        float* Bs = dyn + cur * G2_BUF + G2_ASZ;

        if (kt + 1 < nt) {
            int k0 = (kt + 1) * BK;
            #pragma unroll
            for (int h = 0; h < 4; h++) {
                int gr = rowBase + a_r0 + h * 32;
                a_pf[h] = make_float4(0.f, 0.f, 0.f, 0.f);
                if (gr < M)
                    a_pf[h] = *reinterpret_cast<const float4*>(&A[(size_t)gr * K + k0 + a_c]);
            }
            #pragma unroll
            for (int h = 0; h < 2; h++)
                b_pf[h] = *reinterpret_cast<const float4*>(&B[(size_t)(k0 + b_r0 + h * 16) * N + b_c]);
        }

        #pragma unroll
        for (int k8 = 0; k8 < BK; k8 += 8) {
            wmma::fragment<wmma::matrix_a, 16, 16, 8, wmma::precision::tf32, wmma::row_major> af[2];
            wmma::fragment<wmma::matrix_b, 16, 16, 8, wmma::precision::tf32, wmma::row_major> bf[2];
            #pragma unroll
            for (int i = 0; i < 2; i++)
                wmma::load_matrix_sync(af[i], &As[(warpRow * 32 + i * 16) * G2_LDA + k8], G2_LDA);
            #pragma unroll
            for (int j = 0; j < 2; j++)
                wmma::load_matrix_sync(bf[j], &Bs[k8 * G2_LDB + warpCol * 32 + j * 16], G2_LDB);
            #pragma unroll
            for (int i = 0; i < 2; i++)
                #pragma unroll
                for (int j = 0; j < 2; j++)
                    wmma::mma_sync(acc[i][j], af[i], bf[j], acc[i][j]);
        }

        if (kt + 1 < nt) {
            float* Asn = dyn + (cur ^ 1) * G2_BUF;
            float* Bsn = dyn + (cur ^ 1) * G2_BUF + G2_ASZ;
            #pragma unroll
            for (int h = 0; h < 4; h++) {
                float4 va = a_pf[h];
                va.x = wmma::__float_to_tf32(va.x);  va.y = wmma::__float_to_tf32(va.y);
                va.z = wmma::__float_to_tf32(va.z);  va.w = wmma::__float_to_tf32(va.w);
                *reinterpret_cast<float4*>(&Asn[(a_r0 + h * 32) * G2_LDA + a_c]) = va;
            }
            #pragma unroll
            for (int h = 0; h < 2; h++) {
                float4 vb = b_pf[h];
                vb.x = wmma::__float_to_tf32(vb.x);  vb.y = wmma::__float_to_tf32(vb.y);
                vb.z = wmma::__float_to_tf32(vb.z);  vb.w = wmma::__float_to_tf32(vb.w);
                *reinterpret_cast<float4*>(&Bsn[(b_r0 + h * 16) * G2_LDB + b_c]) = vb;
            }
        }
        __syncthreads();
    }

    #pragma unroll
    for (int i = 0; i < 2; i++) {
        int r0 = rowBase + warpRow * 32 + i * 16;
        #pragma unroll
        for (int j = 0; j < 2; j++) {
            int c0 = warpCol * 32 + j * 16;
            wmma::store_matrix_sync(&g_h2[(size_t)r0 * N + c0], acc[i][j], N,
                                    wmma::mem_row_major);
        }
    }
}

// ---------------- layer-1 aggregation: 4 nodes/block, float4, parallel w ----
__global__ void __launch_bounds__(256) k_agg1(const float* __restrict__ b1, int n) {
    int g = threadIdx.x >> 6;
    int l = threadIdx.x & 63;
    int d = blockIdx.x * 4 + g;
    if (d >= n) return;

    const float4* h1v = reinterpret_cast<const float4*>(g_h1);
    float dd = g_dinv[d];
    float4 self = h1v[(size_t)d * 64 + l];
    float4 acc = make_float4(dd * self.x, dd * self.y, dd * self.z, dd * self.w);

    int beg = g_indptr[d], end = g_indptr[d + 1];
    #pragma unroll 4
    for (int t = beg; t < end; t++) {
        int s = g_srcs[t];
        float w = g_wsrc[t];
        float4 v = h1v[(size_t)s * 64 + l];
        acc.x = fmaf(w, v.x, acc.x);
        acc.y = fmaf(w, v.y, acc.y);
        acc.z = fmaf(w, v.z, acc.z);
        acc.w = fmaf(w, v.w, acc.w);
    }

    float4 b = reinterpret_cast<const float4*>(b1)[l];
    float4 o;
    o.x = fmaxf(fmaf(dd, acc.x, b.x), 0.0f);
    o.y = fmaxf(fmaf(dd, acc.y, b.y), 0.0f);
    o.z = fmaxf(fmaf(dd, acc.z, b.z), 0.0f);
    o.w = fmaxf(fmaf(dd, acc.w, b.w), 0.0f);
    reinterpret_cast<float4*>(g_agg1)[(size_t)d * 64 + l] = o;
}

// ---------------- layer-2 agg + bias + log_softmax (barrier-free) -----------
__global__ void __launch_bounds__(256) k_agg2_lsm(const float* __restrict__ b2,
                                                  float* __restrict__ out, int n) {
    int g = threadIdx.x >> 4;
    int l = threadIdx.x & 15;
    int d = blockIdx.x * 16 + g;
    if (d >= n) return;

    const float4* h2v = reinterpret_cast<const float4*>(g_h2);
    float dd = g_dinv[d];
    float4 self = h2v[(size_t)d * 16 + l];
    float4 acc = make_float4(dd * self.x, dd * self.y, dd * self.z, dd * self.w);

    int beg = g_indptr[d], end = g_indptr[d + 1];
    #pragma unroll 4
    for (int t = beg; t < end; t++) {
        int s = g_srcs[t];
        float w = g_wsrc[t];
        float4 v = h2v[(size_t)s * 16 + l];
        acc.x = fmaf(w, v.x, acc.x);
        acc.y = fmaf(w, v.y, acc.y);
        acc.z = fmaf(w, v.z, acc.z);
        acc.w = fmaf(w, v.w, acc.w);
    }

    float4 b = reinterpret_cast<const float4*>(b2)[l];
    float4 v4;
    v4.x = fmaf(dd, acc.x, b.x);
    v4.y = fmaf(dd, acc.y, b.y);
    v4.z = fmaf(dd, acc.z, b.z);
    v4.w = fmaf(dd, acc.w, b.w);

    float m = fmaxf(fmaxf(v4.x, v4.y), fmaxf(v4.z, v4.w));
    #pragma unroll
    for (int o = 8; o; o >>= 1) m = fmaxf(m, __shfl_xor_sync(0xffffffffu, m, o));
    float s = expf(v4.x - m) + expf(v4.y - m) + expf(v4.z - m) + expf(v4.w - m);
    #pragma unroll
    for (int o = 8; o; o >>= 1) s += __shfl_xor_sync(0xffffffffu, s, o);
    float lse = m + logf(s);

    float4 o4;
    o4.x = v4.x - lse;  o4.y = v4.y - lse;
    o4.z = v4.z - lse;  o4.w = v4.w - lse;
    reinterpret_cast<float4*>(out)[(size_t)d * 16 + l] = o4;
}

// ---------------- entry -----------------------------------------------------
extern "C" void kernel_launch(void* const* d_in, const int* in_sizes, int n_in,
                              void* d_out, int out_size) {
    const float* x  = nullptr;
    const int*   ei = nullptr;
    const float* W1 = nullptr;
    const float* b1 = nullptr;
    const float* W2 = nullptr;
    const float* b2 = nullptr;

    for (int i = 0; i < n_in; i++) {
        long long s = in_sizes[i];
        if      (s == (long long)NODES_MAX * INC)   x  = (const float*)d_in[i];
        else if (s == 2LL * EDGES_MAX)              ei = (const int*)d_in[i];
        else if (s == (long long)INC * HID)         W1 = (const float*)d_in[i];
        else if (s == HID)                          b1 = (const float*)d_in[i];
        else if (s == (long long)HID * OUTC)        W2 = (const float*)d_in[i];
        else if (s == OUTC)                         b2 = (const float*)d_in[i];
    }
    if (!x  && n_in > 0) x  = (const float*)d_in[0];
    if (!ei && n_in > 1) ei = (const int*)d_in[1];
    if (!W1 && n_in > 2) W1 = (const float*)d_in[2];
    if (!b1 && n_in > 3) b1 = (const float*)d_in[3];
    if (!W2 && n_in > 4) W2 = (const float*)d_in[4];
    if (!b2 && n_in > 5) b2 = (const float*)d_in[5];

    float* out = (float*)d_out;

    int E  = EDGES_MAX;
    int Nn = out_size / OUTC;
    if (Nn > NODES_MAX) Nn = NODES_MAX;

    const int* src = ei;
    const int* dst = ei + E;

    int nb = (Nn + 255) / 256;
    int eb = (E + 255) / 256;

    // raise dynamic smem caps (host-side, idempotent, adds no graph node)
    static bool attr_done = false;
    if (!attr_done) {
        cudaFuncSetAttribute(k_gemm1_wmma,
                             cudaFuncAttributeMaxDynamicSharedMemorySize, G1_SMEM);
        cudaFuncSetAttribute(k_gemm2_wmma,
                             cudaFuncAttributeMaxDynamicSharedMemorySize, G2_SMEM);
        attr_done = true;
    }

    k_zero_cnt<<<nb, 256>>>(Nn);
    k_count<<<eb, 256>>>(dst, E, Nn);
    k_scan2<<<1, 1024>>>(Nn);
    k_fill<<<eb, 256>>>(src, dst, E, Nn);

    // layer 1: h1 = x @ W1 (tf32 wmma v3, double-buffered)
    {
        dim3 grid(HID / 128, (Nn + 127) / 128);
        k_gemm1_wmma<<<grid, 256, G1_SMEM>>>(x, W1, Nn, HID, INC);
    }
    k_agg1<<<(Nn + 3) / 4, 256>>>(b1, Nn);

    // layer 2: h2 = g_agg1 @ W2 (tf32 wmma, double-buffered) + fused agg/lsm
    k_gemm2_wmma<<<(Nn + 127) / 128, 256, G2_SMEM>>>(W2, Nn);
    k_agg2_lsm<<<(Nn + 15) / 16, 256>>>(b2, out, Nn);
}

// round 13
// speedup vs baseline: 1.7816x; 1.0984x over previous
#include <cuda_runtime.h>
#include <math.h>
#include <mma.h>

using namespace nvcuda;

#define NODES_MAX 50000
#define M_PAD 50048          // 391 * 128, wmma epilogue padding
#define HID 256
#define OUTC 64
#define INC 512
#define EDGES_MAX 800000

// ---------------- scratch (static __device__ per allocation rules) ----------
__device__ float g_h1[(size_t)M_PAD * HID];         // x @ W1 (padded rows)
__device__ float g_agg1[(size_t)NODES_MAX * HID];   // relu(norm-agg(h1) + b1)
__device__ float g_h2[(size_t)M_PAD * OUTC];        // agg1 @ W2 (padded rows)
__device__ float g_dinv[NODES_MAX];
__device__ int   g_cnt[NODES_MAX];
__device__ int   g_indptr[NODES_MAX + 1];
__device__ int   g_cursor[NODES_MAX];
__device__ int   g_srcs[EDGES_MAX];
__device__ float g_wsrc[EDGES_MAX];                 // dinv[src] per CSR slot

// ---------------- graph preprocessing ---------------------------------------
__global__ void k_zero_cnt(int n) {
    int i = blockIdx.x * blockDim.x + threadIdx.x;
    if (i < n) g_cnt[i] = 0;
}

__global__ void k_count(const int* __restrict__ dst, int E, int n) {
    int i = blockIdx.x * blockDim.x + threadIdx.x;
    if (i < E) {
        int d = dst[i];
        d = max(0, min(n - 1, d));
        atomicAdd(&g_cnt[d], 1);
    }
}

__global__ void __launch_bounds__(1024) k_scan2(int n) {
    const int T = 1024;
    int tid = threadIdx.x;
    int chunk = (n + T - 1) / T;
    int beg = tid * chunk;
    int end = min(beg + chunk, n);

    int sum = 0;
    for (int i = beg; i < end; i++) sum += g_cnt[i];

    int lane = tid & 31, wid = tid >> 5;
    int v = sum;
    #pragma unroll
    for (int off = 1; off < 32; off <<= 1) {
        int t = __shfl_up_sync(0xffffffffu, v, off);
        if (lane >= off) v += t;
    }
    __shared__ int wsum[32];
    if (lane == 31) wsum[wid] = v;
    __syncthreads();
    if (wid == 0) {
        int w = wsum[lane];
        #pragma unroll
        for (int off = 1; off < 32; off <<= 1) {
            int t = __shfl_up_sync(0xffffffffu, w, off);
            if (lane >= off) w += t;
        }
        wsum[lane] = w;
    }
    __syncthreads();
    int excl = v - sum + (wid ? wsum[wid - 1] : 0);

    int run = excl;
    for (int i = beg; i < end; i++) {
        int c = g_cnt[i];
        g_indptr[i] = run;
        g_cursor[i] = run;
        g_dinv[i] = rsqrtf((float)(c + 1));
        run += c;
    }
    if (tid == 0) g_indptr[n] = wsum[31];
}

__global__ void k_fill(const int* __restrict__ src,
                       const int* __restrict__ dst, int E, int n) {
    int i = blockIdx.x * blockDim.x + threadIdx.x;
    if (i < E) {
        int d = dst[i];
        int s = src[i];
        d = max(0, min(n - 1, d));
        s = max(0, min(n - 1, s));
        int p = atomicAdd(&g_cursor[d], 1);
        if (p >= 0 && p < EDGES_MAX) {
            g_srcs[p] = s;
            g_wsrc[p] = g_dinv[s];
        }
    }
}

// ---------------- GEMM1: tf32 wmma v3 (double-buffered smem) ----------------
#define G1_LDA 36
#define G1_LDB 132
#define G1_ASZ (128 * G1_LDA)
#define G1_BSZ (32 * G1_LDB)
#define G1_BUF (G1_ASZ + G1_BSZ)
#define G1_SMEM (2 * G1_BUF * 4)

__global__ void __launch_bounds__(256, 2) k_gemm1_wmma(const float* __restrict__ A,
                                                       const float* __restrict__ B,
                                                       int M, int N, int K) {
    const int BM = 128, BK = 32;
    extern __shared__ __align__(16) float dyn[];

    const int tid = threadIdx.x;
    const int wid = tid >> 5;
    const int warpRow = wid >> 2;
    const int warpCol = wid & 3;
    const int rowBase = blockIdx.y * BM;
    const int colBase = blockIdx.x * 128;

    const int a_r0 = tid >> 3;
    const int a_c  = (tid & 7) * 4;
    const int b_r0 = tid >> 5;
    const int b_c  = (tid & 31) * 4;

    wmma::fragment<wmma::accumulator, 16, 16, 8, float> acc[4][2];
    #pragma unroll
    for (int i = 0; i < 4; i++)
        #pragma unroll
        for (int j = 0; j < 2; j++)
            wmma::fill_fragment(acc[i][j], 0.0f);

    float4 a_pf[4], b_pf[4];

    #pragma unroll
    for (int h = 0; h < 4; h++) {
        int gr = rowBase + a_r0 + h * 32;
        a_pf[h] = make_float4(0.f, 0.f, 0.f, 0.f);
        if (gr < M) a_pf[h] = *reinterpret_cast<const float4*>(&A[(size_t)gr * K + a_c]);
        b_pf[h] = *reinterpret_cast<const float4*>(&B[(size_t)(b_r0 + h * 8) * N + colBase + b_c]);
    }
    {
        float* As = dyn;
        float* Bs = dyn + G1_ASZ;
        #pragma unroll
        for (int h = 0; h < 4; h++) {
            float4 va = a_pf[h];
            va.x = wmma::__float_to_tf32(va.x);  va.y = wmma::__float_to_tf32(va.y);
            va.z = wmma::__float_to_tf32(va.z);  va.w = wmma::__float_to_tf32(va.w);
            *reinterpret_cast<float4*>(&As[(a_r0 + h * 32) * G1_LDA + a_c]) = va;
            float4 vb = b_pf[h];
            vb.x = wmma::__float_to_tf32(vb.x);  vb.y = wmma::__float_to_tf32(vb.y);
            vb.z = wmma::__float_to_tf32(vb.z);  vb.w = wmma::__float_to_tf32(vb.w);
            *reinterpret_cast<float4*>(&Bs[(b_r0 + h * 8) * G1_LDB + b_c]) = vb;
        }
    }
    __syncthreads();

    const int nt = K / BK;
    for (int kt = 0; kt < nt; kt++) {
        const int cur = kt & 1;
        float* As = dyn + cur * G1_BUF;
        float* Bs = dyn + cur * G1_BUF + G1_ASZ;

        if (kt + 1 < nt) {
            int k0 = (kt + 1) * BK;
            #pragma unroll
            for (int h = 0; h < 4; h++) {
                int gr = rowBase + a_r0 + h * 32;
                a_pf[h] = make_float4(0.f, 0.f, 0.f, 0.f);
                if (gr < M)
                    a_pf[h] = *reinterpret_cast<const float4*>(&A[(size_t)gr * K + k0 + a_c]);
                b_pf[h] = *reinterpret_cast<const float4*>(&B[(size_t)(k0 + b_r0 + h * 8) * N + colBase + b_c]);
            }
        }

        #pragma unroll
        for (int k8 = 0; k8 < BK; k8 += 8) {
            wmma::fragment<wmma::matrix_a, 16, 16, 8, wmma::precision::tf32, wmma::row_major> af[4];
            wmma::fragment<wmma::matrix_b, 16, 16, 8, wmma::precision::tf32, wmma::row_major> bf[2];
            #pragma unroll
            for (int i = 0; i < 4; i++)
                wmma::load_matrix_sync(af[i], &As[(warpRow * 64 + i * 16) * G1_LDA + k8], G1_LDA);
            #pragma unroll
            for (int j = 0; j < 2; j++)
                wmma::load_matrix_sync(bf[j], &Bs[k8 * G1_LDB + warpCol * 32 + j * 16], G1_LDB);
            #pragma unroll
            for (int i = 0; i < 4; i++)
                #pragma unroll
                for (int j = 0; j < 2; j++)
                    wmma::mma_sync(acc[i][j], af[i], bf[j], acc[i][j]);
        }

        if (kt + 1 < nt) {
            float* Asn = dyn + (cur ^ 1) * G1_BUF;
            float* Bsn = dyn + (cur ^ 1) * G1_BUF + G1_ASZ;
            #pragma unroll
            for (int h = 0; h < 4; h++) {
                float4 va = a_pf[h];
                va.x = wmma::__float_to_tf32(va.x);  va.y = wmma::__float_to_tf32(va.y);
                va.z = wmma::__float_to_tf32(va.z);  va.w = wmma::__float_to_tf32(va.w);
                *reinterpret_cast<float4*>(&Asn[(a_r0 + h * 32) * G1_LDA + a_c]) = va;
                float4 vb = b_pf[h];
                vb.x = wmma::__float_to_tf32(vb.x);  vb.y = wmma::__float_to_tf32(vb.y);
                vb.z = wmma::__float_to_tf32(vb.z);  vb.w = wmma::__float_to_tf32(vb.w);
                *reinterpret_cast<float4*>(&Bsn[(b_r0 + h * 8) * G1_LDB + b_c]) = vb;
            }
        }
        __syncthreads();
    }

    #pragma unroll
    for (int i = 0; i < 4; i++) {
        int r0 = rowBase + warpRow * 64 + i * 16;
        #pragma unroll
        for (int j = 0; j < 2; j++) {
            int c0 = colBase + warpCol * 32 + j * 16;
            wmma::store_matrix_sync(&g_h1[(size_t)r0 * N + c0], acc[i][j], N,
                                    wmma::mem_row_major);
        }
    }
}

// ---------------- GEMM2: tf32 wmma (double-buffered), g_h2 = g_agg1 @ B -----
#define G2_LDA 36
#define G2_LDB 68
#define G2_ASZ (128 * G2_LDA)
#define G2_BSZ (32 * G2_LDB)
#define G2_BUF (G2_ASZ + G2_BSZ)
#define G2_SMEM (2 * G2_BUF * 4)

__global__ void __launch_bounds__(256, 2) k_gemm2_wmma(const float* __restrict__ B,
                                                       int M) {
    const int BM = 128, BK = 32, K = HID, N = OUTC;
    extern __shared__ __align__(16) float dyn[];

    const float* A = g_agg1;

    const int tid = threadIdx.x;
    const int wid = tid >> 5;
    const int warpRow = wid >> 1;
    const int warpCol = wid & 1;
    const int rowBase = blockIdx.x * BM;

    const int a_r0 = tid >> 3;
    const int a_c  = (tid & 7) * 4;
    const int b_r0 = tid >> 4;
    const int b_c  = (tid & 15) * 4;

    wmma::fragment<wmma::accumulator, 16, 16, 8, float> acc[2][2];
    #pragma unroll
    for (int i = 0; i < 2; i++)
        #pragma unroll
        for (int j = 0; j < 2; j++)
            wmma::fill_fragment(acc[i][j], 0.0f);

    float4 a_pf[4], b_pf[2];

    #pragma unroll
    for (int h = 0; h < 4; h++) {
        int gr = rowBase + a_r0 + h * 32;
        a_pf[h] = make_float4(0.f, 0.f, 0.f, 0.f);
        if (gr < M) a_pf[h] = *reinterpret_cast<const float4*>(&A[(size_t)gr * K + a_c]);
    }
    #pragma unroll
    for (int h = 0; h < 2; h++)
        b_pf[h] = *reinterpret_cast<const float4*>(&B[(size_t)(b_r0 + h * 16) * N + b_c]);

    {
        float* As = dyn;
        float* Bs = dyn + G2_ASZ;
        #pragma unroll
        for (int h = 0; h < 4; h++) {
            float4 va = a_pf[h];
            va.x = wmma::__float_to_tf32(va.x);  va.y = wmma::__float_to_tf32(va.y);
            va.z = wmma::__float_to_tf32(va.z);  va.w = wmma::__float_to_tf32(va.w);
            *reinterpret_cast<float4*>(&As[(a_r0 + h * 32) * G2_LDA + a_c]) = va;
        }
        #pragma unroll
        for (int h = 0; h < 2; h++) {
            float4 vb = b_pf[h];
            vb.x = wmma::__float_to_tf32(vb.x);  vb.y = wmma::__float_to_tf32(vb.y);
            vb.z = wmma::__float_to_tf32(vb.z);  vb.w = wmma::__float_to_tf32(vb.w);
            *reinterpret_cast<float4*>(&Bs[(b_r0 + h * 16) * G2_LDB + b_c]) = vb;
        }
    }
    __syncthreads();

    const int nt = K / BK;
    for (int kt = 0; kt < nt; kt++) {
        const int cur = kt & 1;
        float* As = dyn + cur * G2_BUF;
        float* Bs = dyn + cur * G2_BUF + G2_ASZ;

        if (kt + 1 < nt) {
            int k0 = (kt + 1) * BK;
            #pragma unroll
            for (int h = 0; h < 4; h++) {
                int gr = rowBase + a_r0 + h * 32;
                a_pf[h] = make_float4(0.f, 0.f, 0.f, 0.f);
                if (gr < M)
                    a_pf[h] = *reinterpret_cast<const float4*>(&A[(size_t)gr * K + k0 + a_c]);
            }
            #pragma unroll
            for (int h = 0; h < 2; h++)
                b_pf[h] = *reinterpret_cast<const float4*>(&B[(size_t)(k0 + b_r0 + h * 16) * N + b_c]);
        }

        #pragma unroll
        for (int k8 = 0; k8 < BK; k8 += 8) {
            wmma::fragment<wmma::matrix_a, 16, 16, 8, wmma::precision::tf32, wmma::row_major> af[2];
            wmma::fragment<wmma::matrix_b, 16, 16, 8, wmma::precision::tf32, wmma::row_major> bf[2];
            #pragma unroll
            for (int i = 0; i < 2; i++)
                wmma::load_matrix_sync(af[i], &As[(warpRow * 32 + i * 16) * G2_LDA + k8], G2_LDA);
            #pragma unroll
            for (int j = 0; j < 2; j++)
                wmma::load_matrix_sync(bf[j], &Bs[k8 * G2_LDB + warpCol * 32 + j * 16], G2_LDB);
            #pragma unroll
            for (int i = 0; i < 2; i++)
                #pragma unroll
                for (int j = 0; j < 2; j++)
                    wmma::mma_sync(acc[i][j], af[i], bf[j], acc[i][j]);
        }

        if (kt + 1 < nt) {
            float* Asn = dyn + (cur ^ 1) * G2_BUF;
            float* Bsn = dyn + (cur ^ 1) * G2_BUF + G2_ASZ;
            #pragma unroll
            for (int h = 0; h < 4; h++) {
                float4 va = a_pf[h];
                va.x = wmma::__float_to_tf32(va.x);  va.y = wmma::__float_to_tf32(va.y);
                va.z = wmma::__float_to_tf32(va.z);  va.w = wmma::__float_to_tf32(va.w);
                *reinterpret_cast<float4*>(&Asn[(a_r0 + h * 32) * G2_LDA + a_c]) = va;
            }
            #pragma unroll
            for (int h = 0; h < 2; h++) {
                float4 vb = b_pf[h];
                vb.x = wmma::__float_to_tf32(vb.x);  vb.y = wmma::__float_to_tf32(vb.y);
                vb.z = wmma::__float_to_tf32(vb.z);  vb.w = wmma::__float_to_tf32(vb.w);
                *reinterpret_cast<float4*>(&Bsn[(b_r0 + h * 16) * G2_LDB + b_c]) = vb;
            }
        }
        __syncthreads();
    }

    #pragma unroll
    for (int i = 0; i < 2; i++) {
        int r0 = rowBase + warpRow * 32 + i * 16;
        #pragma unroll
        for (int j = 0; j < 2; j++) {
            int c0 = warpCol * 32 + j * 16;
            wmma::store_matrix_sync(&g_h2[(size_t)r0 * N + c0], acc[i][j], N,
                                    wmma::mem_row_major);
        }
    }
}

// ---------------- layer-1 aggregation: 4 nodes/block, float4, unroll 8 ------
__global__ void __launch_bounds__(256) k_agg1(const float* __restrict__ b1, int n) {
    int g = threadIdx.x >> 6;
    int l = threadIdx.x & 63;
    int d = blockIdx.x * 4 + g;
    if (d >= n) return;

    const float4* h1v = reinterpret_cast<const float4*>(g_h1);
    float dd = g_dinv[d];
    float4 self = h1v[(size_t)d * 64 + l];
    float4 acc = make_float4(dd * self.x, dd * self.y, dd * self.z, dd * self.w);

    int beg = g_indptr[d], end = g_indptr[d + 1];
    #pragma unroll 8
    for (int t = beg; t < end; t++) {
        int s = g_srcs[t];
        float w = g_wsrc[t];
        float4 v = h1v[(size_t)s * 64 + l];
        acc.x = fmaf(w, v.x, acc.x);
        acc.y = fmaf(w, v.y, acc.y);
        acc.z = fmaf(w, v.z, acc.z);
        acc.w = fmaf(w, v.w, acc.w);
    }

    float4 b = reinterpret_cast<const float4*>(b1)[l];
    float4 o;
    o.x = fmaxf(fmaf(dd, acc.x, b.x), 0.0f);
    o.y = fmaxf(fmaf(dd, acc.y, b.y), 0.0f);
    o.z = fmaxf(fmaf(dd, acc.z, b.z), 0.0f);
    o.w = fmaxf(fmaf(dd, acc.w, b.w), 0.0f);
    reinterpret_cast<float4*>(g_agg1)[(size_t)d * 64 + l] = o;
}

// ---------------- layer-2 agg + bias + log_softmax (barrier-free) -----------
__global__ void __launch_bounds__(256) k_agg2_lsm(const float* __restrict__ b2,
                                                  float* __restrict__ out, int n) {
    int g = threadIdx.x >> 4;
    int l = threadIdx.x & 15;
    int d = blockIdx.x * 16 + g;
    if (d >= n) return;

    const float4* h2v = reinterpret_cast<const float4*>(g_h2);
    float dd = g_dinv[d];
    float4 self = h2v[(size_t)d * 16 + l];
    float4 acc = make_float4(dd * self.x, dd * self.y, dd * self.z, dd * self.w);

    int beg = g_indptr[d], end = g_indptr[d + 1];
    #pragma unroll 8
    for (int t = beg; t < end; t++) {
        int s = g_srcs[t];
        float w = g_wsrc[t];
        float4 v = h2v[(size_t)s * 16 + l];
        acc.x = fmaf(w, v.x, acc.x);
        acc.y = fmaf(w, v.y, acc.y);
        acc.z = fmaf(w, v.z, acc.z);
        acc.w = fmaf(w, v.w, acc.w);
    }

    float4 b = reinterpret_cast<const float4*>(b2)[l];
    float4 v4;
    v4.x = fmaf(dd, acc.x, b.x);
    v4.y = fmaf(dd, acc.y, b.y);
    v4.z = fmaf(dd, acc.z, b.z);
    v4.w = fmaf(dd, acc.w, b.w);

    float m = fmaxf(fmaxf(v4.x, v4.y), fmaxf(v4.z, v4.w));
    #pragma unroll
    for (int o = 8; o; o >>= 1) m = fmaxf(m, __shfl_xor_sync(0xffffffffu, m, o));
    float s = expf(v4.x - m) + expf(v4.y - m) + expf(v4.z - m) + expf(v4.w - m);
    #pragma unroll
    for (int o = 8; o; o >>= 1) s += __shfl_xor_sync(0xffffffffu, s, o);
    float lse = m + logf(s);

    float4 o4;
    o4.x = v4.x - lse;  o4.y = v4.y - lse;
    o4.z = v4.z - lse;  o4.w = v4.w - lse;
    reinterpret_cast<float4*>(out)[(size_t)d * 16 + l] = o4;
}

// ---------------- entry -----------------------------------------------------
extern "C" void kernel_launch(void* const* d_in, const int* in_sizes, int n_in,
                              void* d_out, int out_size) {
    const float* x  = nullptr;
    const int*   ei = nullptr;
    const float* W1 = nullptr;
    const float* b1 = nullptr;
    const float* W2 = nullptr;
    const float* b2 = nullptr;

    for (int i = 0; i < n_in; i++) {
        long long s = in_sizes[i];
        if      (s == (long long)NODES_MAX * INC)   x  = (const float*)d_in[i];
        else if (s == 2LL * EDGES_MAX)              ei = (const int*)d_in[i];
        else if (s == (long long)INC * HID)         W1 = (const float*)d_in[i];
        else if (s == HID)                          b1 = (const float*)d_in[i];
        else if (s == (long long)HID * OUTC)        W2 = (const float*)d_in[i];
        else if (s == OUTC)                         b2 = (const float*)d_in[i];
    }
    if (!x  && n_in > 0) x  = (const float*)d_in[0];
    if (!ei && n_in > 1) ei = (const int*)d_in[1];
    if (!W1 && n_in > 2) W1 = (const float*)d_in[2];
    if (!b1 && n_in > 3) b1 = (const float*)d_in[3];
    if (!W2 && n_in > 4) W2 = (const float*)d_in[4];
    if (!b2 && n_in > 5) b2 = (const float*)d_in[5];

    float* out = (float*)d_out;

    int E  = EDGES_MAX;
    int Nn = out_size / OUTC;
    if (Nn > NODES_MAX) Nn = NODES_MAX;

    const int* src = ei;
    const int* dst = ei + E;

    int nb = (Nn + 255) / 256;
    int eb = (E + 255) / 256;

    static bool attr_done = false;
    if (!attr_done) {
        cudaFuncSetAttribute(k_gemm1_wmma,
                             cudaFuncAttributeMaxDynamicSharedMemorySize, G1_SMEM);
        cudaFuncSetAttribute(k_gemm2_wmma,
                             cudaFuncAttributeMaxDynamicSharedMemorySize, G2_SMEM);
        attr_done = true;
    }

    // NOTE: gemm1 hoisted to launch index 3 (it has no CSR dependency; the
    // stream serializes everything, so semantics are unchanged) — this puts
    // it in ncu's fixed capture window for per-kernel data.
    k_zero_cnt<<<nb, 256>>>(Nn);
    k_count<<<eb, 256>>>(dst, E, Nn);
    k_scan2<<<1, 1024>>>(Nn);
    {
        dim3 grid(HID / 128, (Nn + 127) / 128);
        k_gemm1_wmma<<<grid, 256, G1_SMEM>>>(x, W1, Nn, HID, INC);   // index 3
    }
    k_fill<<<eb, 256>>>(src, dst, E, Nn);
    k_agg1<<<(Nn + 3) / 4, 256>>>(b1, Nn);
    k_gemm2_wmma<<<(Nn + 127) / 128, 256, G2_SMEM>>>(W2, Nn);
    k_agg2_lsm<<<(Nn + 15) / 16, 256>>>(b2, out, Nn);
}

// round 16
// speedup vs baseline: 2.5466x; 1.4294x over previous
#include <cuda_runtime.h>
#include <cuda_bf16.h>
#include <math.h>
#include <mma.h>
#include <stdint.h>

using namespace nvcuda;

#define NODES_MAX 50000
#define M_PAD 50048          // 391 * 128, wmma epilogue padding
#define HID 256
#define OUTC 64
#define INC 512
#define EDGES_MAX 800000

// ---------------- scratch (static __device__ per allocation rules) ----------
__device__ float g_h1[(size_t)M_PAD * HID];         // x @ W1 (padded rows)
__device__ float g_agg1[(size_t)NODES_MAX * HID];   // relu(norm-agg(h1) + b1)
__device__ float g_h2[(size_t)M_PAD * OUTC];        // agg1 @ W2 (padded rows)
__device__ float g_dinv[NODES_MAX];
__device__ int   g_cnt[NODES_MAX];
__device__ int   g_indptr[NODES_MAX + 1];
__device__ int   g_cursor[NODES_MAX];
__device__ int   g_srcs[EDGES_MAX];
__device__ float g_wsrc[EDGES_MAX];                 // dinv[src] per CSR slot

// ---------------- graph preprocessing ---------------------------------------
__global__ void k_zero_cnt(int n) {
    int i = blockIdx.x * blockDim.x + threadIdx.x;
    if (i < n) g_cnt[i] = 0;
}

__global__ void k_count(const int* __restrict__ dst, int E, int n) {
    int i = blockIdx.x * blockDim.x + threadIdx.x;
    if (i < E) {
        int d = dst[i];
        d = max(0, min(n - 1, d));
        atomicAdd(&g_cnt[d], 1);
    }
}

__global__ void __launch_bounds__(1024) k_scan2(int n) {
    const int T = 1024;
    int tid = threadIdx.x;
    int chunk = (n + T - 1) / T;
    int beg = tid * chunk;
    int end = min(beg + chunk, n);

    int sum = 0;
    for (int i = beg; i < end; i++) sum += g_cnt[i];

    int lane = tid & 31, wid = tid >> 5;
    int v = sum;
    #pragma unroll
    for (int off = 1; off < 32; off <<= 1) {
        int t = __shfl_up_sync(0xffffffffu, v, off);
        if (lane >= off) v += t;
    }
    __shared__ int wsum[32];
    if (lane == 31) wsum[wid] = v;
    __syncthreads();
    if (wid == 0) {
        int w = wsum[lane];
        #pragma unroll
        for (int off = 1; off < 32; off <<= 1) {
            int t = __shfl_up_sync(0xffffffffu, w, off);
            if (lane >= off) w += t;
        }
        wsum[lane] = w;
    }
    __syncthreads();
    int excl = v - sum + (wid ? wsum[wid - 1] : 0);

    int run = excl;
    for (int i = beg; i < end; i++) {
        int c = g_cnt[i];
        g_indptr[i] = run;
        g_cursor[i] = run;
        g_dinv[i] = rsqrtf((float)(c + 1));
        run += c;
    }
    if (tid == 0) g_indptr[n] = wsum[31];
}

__global__ void k_fill(const int* __restrict__ src,
                       const int* __restrict__ dst, int E, int n) {
    int i = blockIdx.x * blockDim.x + threadIdx.x;
    if (i < E) {
        int d = dst[i];
        int s = src[i];
        d = max(0, min(n - 1, d));
        s = max(0, min(n - 1, s));
        int p = atomicAdd(&g_cursor[d], 1);
        if (p >= 0 && p < EDGES_MAX) {
            g_srcs[p] = s;
            g_wsrc[p] = g_dinv[s];
        }
    }
}

// ---------------- GEMM1: bf16 wmma (m16n16k16), double-buffered -------------
// BM=128, BN=128, BK=32. 8 warps (2 rows x 4 cols); warp tile 64x32.
// fp32 -> bf16 conversion happens in staging (no extra global traffic).
// smem: 2 * (128*40 + 32*136) bf16 = 37888 B (< 48 KB default).
#define B1_LDA 40
#define B1_LDB 136
#define B1_ASZ (128 * B1_LDA)
#define B1_BSZ (32 * B1_LDB)
#define B1_BUF (B1_ASZ + B1_BSZ)
#define B1_SMEM (2 * B1_BUF * 2)

__device__ __forceinline__ uint2 f4_to_bf8(float4 v) {
    __nv_bfloat162 lo = __float22bfloat162_rn(make_float2(v.x, v.y));
    __nv_bfloat162 hi = __float22bfloat162_rn(make_float2(v.z, v.w));
    uint2 r;
    r.x = *reinterpret_cast<uint32_t*>(&lo);
    r.y = *reinterpret_cast<uint32_t*>(&hi);
    return r;
}

__global__ void __launch_bounds__(256, 2) k_gemm1_wmma(const float* __restrict__ A,
                                                       const float* __restrict__ B,
                                                       int M, int N, int K) {
    const int BM = 128, BK = 32;
    extern __shared__ __align__(16) __nv_bfloat16 dynb[];

    const int tid = threadIdx.x;
    const int wid = tid >> 5;
    const int warpRow = wid >> 2;      // 0..1 -> m*64
    const int warpCol = wid & 3;       // 0..3 -> n*32
    const int rowBase = blockIdx.y * BM;
    const int colBase = blockIdx.x * 128;

    const int a_r0 = tid >> 3;         // 0..31, +32 per pass (4 passes)
    const int a_c  = (tid & 7) * 4;    // 0..28
    const int b_r0 = tid >> 5;         // 0..7, +8 per pass (4 passes)
    const int b_c  = (tid & 31) * 4;   // 0..124

    wmma::fragment<wmma::accumulator, 16, 16, 16, float> acc[4][2];
    #pragma unroll
    for (int i = 0; i < 4; i++)
        #pragma unroll
        for (int j = 0; j < 2; j++)
            wmma::fill_fragment(acc[i][j], 0.0f);

    float4 a_pf[4], b_pf[4];

    // load + stage tile 0 into buffer 0
    #pragma unroll
    for (int h = 0; h < 4; h++) {
        int gr = rowBase + a_r0 + h * 32;
        a_pf[h] = make_float4(0.f, 0.f, 0.f, 0.f);
        if (gr < M) a_pf[h] = *reinterpret_cast<const float4*>(&A[(size_t)gr * K + a_c]);
        b_pf[h] = *reinterpret_cast<const float4*>(&B[(size_t)(b_r0 + h * 8) * N + colBase + b_c]);
    }
    {
        __nv_bfloat16* As = dynb;
        __nv_bfloat16* Bs = dynb + B1_ASZ;
        #pragma unroll
        for (int h = 0; h < 4; h++) {
            *reinterpret_cast<uint2*>(&As[(a_r0 + h * 32) * B1_LDA + a_c]) = f4_to_bf8(a_pf[h]);
            *reinterpret_cast<uint2*>(&Bs[(b_r0 + h * 8) * B1_LDB + b_c]) = f4_to_bf8(b_pf[h]);
        }
    }
    __syncthreads();

    const int nt = K / BK;   // 16
    for (int kt = 0; kt < nt; kt++) {
        const int cur = kt & 1;
        __nv_bfloat16* As = dynb + cur * B1_BUF;
        __nv_bfloat16* Bs = dynb + cur * B1_BUF + B1_ASZ;

        // prefetch next tile into regs (overlaps MMA)
        if (kt + 1 < nt) {
            int k0 = (kt + 1) * BK;
            #pragma unroll
            for (int h = 0; h < 4; h++) {
                int gr = rowBase + a_r0 + h * 32;
                a_pf[h] = make_float4(0.f, 0.f, 0.f, 0.f);
                if (gr < M)
                    a_pf[h] = *reinterpret_cast<const float4*>(&A[(size_t)gr * K + k0 + a_c]);
                b_pf[h] = *reinterpret_cast<const float4*>(&B[(size_t)(k0 + b_r0 + h * 8) * N + colBase + b_c]);
            }
        }

        // MMA over current tile: 2 k16 steps
        #pragma unroll
        for (int k16 = 0; k16 < BK; k16 += 16) {
            wmma::fragment<wmma::matrix_a, 16, 16, 16, __nv_bfloat16, wmma::row_major> af[4];
            wmma::fragment<wmma::matrix_b, 16, 16, 16, __nv_bfloat16, wmma::row_major> bf[2];
            #pragma unroll
            for (int i = 0; i < 4; i++)
                wmma::load_matrix_sync(af[i], &As[(warpRow * 64 + i * 16) * B1_LDA + k16], B1_LDA);
            #pragma unroll
            for (int j = 0; j < 2; j++)
                wmma::load_matrix_sync(bf[j], &Bs[k16 * B1_LDB + warpCol * 32 + j * 16], B1_LDB);
            #pragma unroll
            for (int i = 0; i < 4; i++)
                #pragma unroll
                for (int j = 0; j < 2; j++)
                    wmma::mma_sync(acc[i][j], af[i], bf[j], acc[i][j]);
        }

        // stage next tile into the alternate buffer
        if (kt + 1 < nt) {
            __nv_bfloat16* Asn = dynb + (cur ^ 1) * B1_BUF;
            __nv_bfloat16* Bsn = dynb + (cur ^ 1) * B1_BUF + B1_ASZ;
            #pragma unroll
            for (int h = 0; h < 4; h++) {
                *reinterpret_cast<uint2*>(&Asn[(a_r0 + h * 32) * B1_LDA + a_c]) = f4_to_bf8(a_pf[h]);
                *reinterpret_cast<uint2*>(&Bsn[(b_r0 + h * 8) * B1_LDB + b_c]) = f4_to_bf8(b_pf[h]);
            }
        }
        __syncthreads();
    }

    // epilogue: unguarded (g_h1 rows padded to M_PAD)
    #pragma unroll
    for (int i = 0; i < 4; i++) {
        int r0 = rowBase + warpRow * 64 + i * 16;
        #pragma unroll
        for (int j = 0; j < 2; j++) {
            int c0 = colBase + warpCol * 32 + j * 16;
            wmma::store_matrix_sync(&g_h1[(size_t)r0 * N + c0], acc[i][j], N,
                                    wmma::mem_row_major);
        }
    }
}

// ---------------- GEMM2: tf32 wmma (double-buffered), g_h2 = g_agg1 @ B -----
#define G2_LDA 36
#define G2_LDB 68
#define G2_ASZ (128 * G2_LDA)
#define G2_BSZ (32 * G2_LDB)
#define G2_BUF (G2_ASZ + G2_BSZ)
#define G2_SMEM (2 * G2_BUF * 4)

__global__ void __launch_bounds__(256, 2) k_gemm2_wmma(const float* __restrict__ B,
                                                       int M) {
    const int BM = 128, BK = 32, K = HID, N = OUTC;
    extern __shared__ __align__(16) float dyn[];

    const float* A = g_agg1;

    const int tid = threadIdx.x;
    const int wid = tid >> 5;
    const int warpRow = wid >> 1;
    const int warpCol = wid & 1;
    const int rowBase = blockIdx.x * BM;

    const int a_r0 = tid >> 3;
    const int a_c  = (tid & 7) * 4;
    const int b_r0 = tid >> 4;
    const int b_c  = (tid & 15) * 4;

    wmma::fragment<wmma::accumulator, 16, 16, 8, float> acc[2][2];
    #pragma unroll
    for (int i = 0; i < 2; i++)
        #pragma unroll
        for (int j = 0; j < 2; j++)
            wmma::fill_fragment(acc[i][j], 0.0f);

    float4 a_pf[4], b_pf[2];

    #pragma unroll
    for (int h = 0; h < 4; h++) {
        int gr = rowBase + a_r0 + h * 32;
        a_pf[h] = make_float4(0.f, 0.f, 0.f, 0.f);
        if (gr < M) a_pf[h] = *reinterpret_cast<const float4*>(&A[(size_t)gr * K + a_c]);
    }
    #pragma unroll
    for (int h = 0; h < 2; h++)
        b_pf[h] = *reinterpret_cast<const float4*>(&B[(size_t)(b_r0 + h * 16) * N + b_c]);

    {
        float* As = dyn;
        float* Bs = dyn + G2_ASZ;
        #pragma unroll
        for (int h = 0; h < 4; h++) {
            float4 va = a_pf[h];
            va.x = wmma::__float_to_tf32(va.x);  va.y = wmma::__float_to_tf32(va.y);
            va.z = wmma::__float_to_tf32(va.z);  va.w = wmma::__float_to_tf32(va.w);
            *reinterpret_cast<float4*>(&As[(a_r0 + h * 32) * G2_LDA + a_c]) = va;
        }
        #pragma unroll
        for (int h = 0; h < 2; h++) {
            float4 vb = b_pf[h];
            vb.x = wmma::__float_to_tf32(vb.x);  vb.y = wmma::__float_to_tf32(vb.y);
            vb.z = wmma::__float_to_tf32(vb.z);  vb.w = wmma::__float_to_tf32(vb.w);
            *reinterpret_cast<float4*>(&Bs[(b_r0 + h * 16) * G2_LDB + b_c]) = vb;
        }
    }
    __syncthreads();

    const int nt = K / BK;
    for (int kt = 0; kt < nt; kt++) {
        const int cur = kt & 1;
        float* As = dyn + cur * G2_BUF;
        float* Bs = dyn + cur * G2_BUF + G2_ASZ;

        if (kt + 1 < nt) {
            int k0 = (kt + 1) * BK;
            #pragma unroll
            for (int h = 0; h < 4; h++) {
                int gr = rowBase + a_r0 + h * 32;
                a_pf[h] = make_float4(0.f, 0.f, 0.f, 0.f);
                if (gr < M)
                    a_pf[h] = *reinterpret_cast<const float4*>(&A[(size_t)gr * K + k0 + a_c]);
            }
            #pragma unroll
            for (int h = 0; h < 2; h++)
                b_pf[h] = *reinterpret_cast<const float4*>(&B[(size_t)(k0 + b_r0 + h * 16) * N + b_c]);
        }

        #pragma unroll
        for (int k8 = 0; k8 < BK; k8 += 8) {
            wmma::fragment<wmma::matrix_a, 16, 16, 8, wmma::precision::tf32, wmma::row_major> af[2];
            wmma::fragment<wmma::matrix_b, 16, 16, 8, wmma::precision::tf32, wmma::row_major> bf[2];
            #pragma unroll
            for (int i = 0; i < 2; i++)
                wmma::load_matrix_sync(af[i], &As[(warpRow * 32 + i * 16) * G2_LDA + k8], G2_LDA);
            #pragma unroll
            for (int j = 0; j < 2; j++)
                wmma::load_matrix_sync(bf[j], &Bs[k8 * G2_LDB + warpCol * 32 + j * 16], G2_LDB);
            #pragma unroll
            for (int i = 0; i < 2; i++)
                #pragma unroll
                for (int j = 0; j < 2; j++)
                    wmma::mma_sync(acc[i][j], af[i], bf[j], acc[i][j]);
        }

        if (kt + 1 < nt) {
            float* Asn = dyn + (cur ^ 1) * G2_BUF;
            float* Bsn = dyn + (cur ^ 1) * G2_BUF + G2_ASZ;
            #pragma unroll
            for (int h = 0; h < 4; h++) {
                float4 va = a_pf[h];
                va.x = wmma::__float_to_tf32(va.x);  va.y = wmma::__float_to_tf32(va.y);
                va.z = wmma::__float_to_tf32(va.z);  va.w = wmma::__float_to_tf32(va.w);
                *reinterpret_cast<float4*>(&Asn[(a_r0 + h * 32) * G2_LDA + a_c]) = va;
            }
            #pragma unroll
            for (int h = 0; h < 2; h++) {
                float4 vb = b_pf[h];
                vb.x = wmma::__float_to_tf32(vb.x);  vb.y = wmma::__float_to_tf32(vb.y);
                vb.z = wmma::__float_to_tf32(vb.z);  vb.w = wmma::__float_to_tf32(vb.w);
                *reinterpret_cast<float4*>(&Bsn[(b_r0 + h * 16) * G2_LDB + b_c]) = vb;
            }
        }
        __syncthreads();
    }

    #pragma unroll
    for (int i = 0; i < 2; i++) {
        int r0 = rowBase + warpRow * 32 + i * 16;
        #pragma unroll
        for (int j = 0; j < 2; j++) {
            int c0 = warpCol * 32 + j * 16;
            wmma::store_matrix_sync(&g_h2[(size_t)r0 * N + c0], acc[i][j], N,
                                    wmma::mem_row_major);
        }
    }
}

// ---------------- layer-1 aggregation: 4 nodes/block, float4, unroll 8 ------
__global__ void __launch_bounds__(256) k_agg1(const float* __restrict__ b1, int n) {
    int g = threadIdx.x >> 6;
    int l = threadIdx.x & 63;
    int d = blockIdx.x * 4 + g;
    if (d >= n) return;

    const float4* h1v = reinterpret_cast<const float4*>(g_h1);
    float dd = g_dinv[d];
    float4 self = h1v[(size_t)d * 64 + l];
    float4 acc = make_float4(dd * self.x, dd * self.y, dd * self.z, dd * self.w);

    int beg = g_indptr[d], end = g_indptr[d + 1];
    #pragma unroll 8
    for (int t = beg; t < end; t++) {
        int s = g_srcs[t];
        float w = g_wsrc[t];
        float4 v = h1v[(size_t)s * 64 + l];
        acc.x = fmaf(w, v.x, acc.x);
        acc.y = fmaf(w, v.y, acc.y);
        acc.z = fmaf(w, v.z, acc.z);
        acc.w = fmaf(w, v.w, acc.w);
    }

    float4 b = reinterpret_cast<const float4*>(b1)[l];
    float4 o;
    o.x = fmaxf(fmaf(dd, acc.x, b.x), 0.0f);
    o.y = fmaxf(fmaf(dd, acc.y, b.y), 0.0f);
    o.z = fmaxf(fmaf(dd, acc.z, b.z), 0.0f);
    o.w = fmaxf(fmaf(dd, acc.w, b.w), 0.0f);
    reinterpret_cast<float4*>(g_agg1)[(size_t)d * 64 + l] = o;
}

// ---------------- layer-2 agg + bias + log_softmax (barrier-free) -----------
__global__ void __launch_bounds__(256) k_agg2_lsm(const float* __restrict__ b2,
                                                  float* __restrict__ out, int n) {
    int g = threadIdx.x >> 4;
    int l = threadIdx.x & 15;
    int d = blockIdx.x * 16 + g;
    if (d >= n) return;

    const float4* h2v = reinterpret_cast<const float4*>(g_h2);
    float dd = g_dinv[d];
    float4 self = h2v[(size_t)d * 16 + l];
    float4 acc = make_float4(dd * self.x, dd * self.y, dd * self.z, dd * self.w);

    int beg = g_indptr[d], end = g_indptr[d + 1];
    #pragma unroll 8
    for (int t = beg; t < end; t++) {
        int s = g_srcs[t];
        float w = g_wsrc[t];
        float4 v = h2v[(size_t)s * 16 + l];
        acc.x = fmaf(w, v.x, acc.x);
        acc.y = fmaf(w, v.y, acc.y);
        acc.z = fmaf(w, v.z, acc.z);
        acc.w = fmaf(w, v.w, acc.w);
    }

    float4 b = reinterpret_cast<const float4*>(b2)[l];
    float4 v4;
    v4.x = fmaf(dd, acc.x, b.x);
    v4.y = fmaf(dd, acc.y, b.y);
    v4.z = fmaf(dd, acc.z, b.z);
    v4.w = fmaf(dd, acc.w, b.w);

    float m = fmaxf(fmaxf(v4.x, v4.y), fmaxf(v4.z, v4.w));
    #pragma unroll
    for (int o = 8; o; o >>= 1) m = fmaxf(m, __shfl_xor_sync(0xffffffffu, m, o));
    float s = expf(v4.x - m) + expf(v4.y - m) + expf(v4.z - m) + expf(v4.w - m);
    #pragma unroll
    for (int o = 8; o; o >>= 1) s += __shfl_xor_sync(0xffffffffu, s, o);
    float lse = m + logf(s);

    float4 o4;
    o4.x = v4.x - lse;  o4.y = v4.y - lse;
    o4.z = v4.z - lse;  o4.w = v4.w - lse;
    reinterpret_cast<float4*>(out)[(size_t)d * 16 + l] = o4;
}

// ---------------- entry -----------------------------------------------------
extern "C" void kernel_launch(void* const* d_in, const int* in_sizes, int n_in,
                              void* d_out, int out_size) {
    const float* x  = nullptr;
    const int*   ei = nullptr;
    const float* W1 = nullptr;
    const float* b1 = nullptr;
    const float* W2 = nullptr;
    const float* b2 = nullptr;

    for (int i = 0; i < n_in; i++) {
        long long s = in_sizes[i];
        if      (s == (long long)NODES_MAX * INC)   x  = (const float*)d_in[i];
        else if (s == 2LL * EDGES_MAX)              ei = (const int*)d_in[i];
        else if (s == (long long)INC * HID)         W1 = (const float*)d_in[i];
        else if (s == HID)                          b1 = (const float*)d_in[i];
        else if (s == (long long)HID * OUTC)        W2 = (const float*)d_in[i];
        else if (s == OUTC)                         b2 = (const float*)d_in[i];
    }
    if (!x  && n_in > 0) x  = (const float*)d_in[0];
    if (!ei && n_in > 1) ei = (const int*)d_in[1];
    if (!W1 && n_in > 2) W1 = (const float*)d_in[2];
    if (!b1 && n_in > 3) b1 = (const float*)d_in[3];
    if (!W2 && n_in > 4) W2 = (const float*)d_in[4];
    if (!b2 && n_in > 5) b2 = (const float*)d_in[5];

    float* out = (float*)d_out;

    int E  = EDGES_MAX;
    int Nn = out_size / OUTC;
    if (Nn > NODES_MAX) Nn = NODES_MAX;

    const int* src = ei;
    const int* dst = ei + E;

    int nb = (Nn + 255) / 256;
    int eb = (E + 255) / 256;

    static bool attr_done = false;
    if (!attr_done) {
        cudaFuncSetAttribute(k_gemm2_wmma,
                             cudaFuncAttributeMaxDynamicSharedMemorySize, G2_SMEM);
        attr_done = true;
    }

    // gemm1 at launch index 3 (CSR-independent; stream serializes) — keeps it
    // in ncu's fixed capture window.
    k_zero_cnt<<<nb, 256>>>(Nn);
    k_count<<<eb, 256>>>(dst, E, Nn);
    k_scan2<<<1, 1024>>>(Nn);
    {
        dim3 grid(HID / 128, (Nn + 127) / 128);
        k_gemm1_wmma<<<grid, 256, B1_SMEM>>>(x, W1, Nn, HID, INC);   // index 3
    }
    k_fill<<<eb, 256>>>(src, dst, E, Nn);
    k_agg1<<<(Nn + 3) / 4, 256>>>(b1, Nn);
    k_gemm2_wmma<<<(Nn + 127) / 128, 256, G2_SMEM>>>(W2, Nn);
    k_agg2_lsm<<<(Nn + 15) / 16, 256>>>(b2, out, Nn);
}

// round 17
// speedup vs baseline: 2.6724x; 1.0494x over previous
#include <cuda_runtime.h>
#include <cuda_bf16.h>
#include <math.h>
#include <mma.h>
#include <stdint.h>

using namespace nvcuda;

#define NODES_MAX 50000
#define M_PAD 50048          // 391 * 128, wmma epilogue padding
#define HID 256
#define OUTC 64
#define INC 512
#define EDGES_MAX 800000

// ---------------- scratch (static __device__ per allocation rules) ----------
__device__ __nv_bfloat16 g_h1b[(size_t)M_PAD * HID];     // x @ W1 (bf16)
__device__ __nv_bfloat16 g_agg1b[(size_t)M_PAD * HID];   // relu(agg) (bf16)
__device__ float g_h2[(size_t)M_PAD * OUTC];             // agg1 @ W2 (fp32)
__device__ float g_dinv[NODES_MAX];
__device__ int   g_cnt[NODES_MAX];
__device__ int   g_indptr[NODES_MAX + 1];
__device__ int   g_cursor[NODES_MAX];
__device__ int   g_srcs[EDGES_MAX];
__device__ float g_wsrc[EDGES_MAX];                      // dinv[src] per CSR slot

// ---------------- bf16 pack/unpack helpers -----------------------------------
__device__ __forceinline__ uint2 f4_to_bf8(float4 v) {
    __nv_bfloat162 lo = __float22bfloat162_rn(make_float2(v.x, v.y));
    __nv_bfloat162 hi = __float22bfloat162_rn(make_float2(v.z, v.w));
    uint2 r;
    r.x = *reinterpret_cast<uint32_t*>(&lo);
    r.y = *reinterpret_cast<uint32_t*>(&hi);
    return r;
}
__device__ __forceinline__ float4 bf8_to_f4(uint2 r) {
    __nv_bfloat162 lo = *reinterpret_cast<__nv_bfloat162*>(&r.x);
    __nv_bfloat162 hi = *reinterpret_cast<__nv_bfloat162*>(&r.y);
    float2 a = __bfloat1622float2(lo);
    float2 b = __bfloat1622float2(hi);
    return make_float4(a.x, a.y, b.x, b.y);
}

// ---------------- graph preprocessing ---------------------------------------
__global__ void k_zero_cnt(int n) {
    int i = blockIdx.x * blockDim.x + threadIdx.x;
    if (i < n) g_cnt[i] = 0;
}

__global__ void k_count(const int* __restrict__ dst, int E, int n) {
    int i = blockIdx.x * blockDim.x + threadIdx.x;
    if (i < E) {
        int d = dst[i];
        d = max(0, min(n - 1, d));
        atomicAdd(&g_cnt[d], 1);
    }
}

__global__ void __launch_bounds__(1024) k_scan2(int n) {
    const int T = 1024;
    int tid = threadIdx.x;
    int chunk = (n + T - 1) / T;
    int beg = tid * chunk;
    int end = min(beg + chunk, n);

    int sum = 0;
    for (int i = beg; i < end; i++) sum += g_cnt[i];

    int lane = tid & 31, wid = tid >> 5;
    int v = sum;
    #pragma unroll
    for (int off = 1; off < 32; off <<= 1) {
        int t = __shfl_up_sync(0xffffffffu, v, off);
        if (lane >= off) v += t;
    }
    __shared__ int wsum[32];
    if (lane == 31) wsum[wid] = v;
    __syncthreads();
    if (wid == 0) {
        int w = wsum[lane];
        #pragma unroll
        for (int off = 1; off < 32; off <<= 1) {
            int t = __shfl_up_sync(0xffffffffu, w, off);
            if (lane >= off) w += t;
        }
        wsum[lane] = w;
    }
    __syncthreads();
    int excl = v - sum + (wid ? wsum[wid - 1] : 0);

    int run = excl;
    for (int i = beg; i < end; i++) {
        int c = g_cnt[i];
        g_indptr[i] = run;
        g_cursor[i] = run;
        g_dinv[i] = rsqrtf((float)(c + 1));
        run += c;
    }
    if (tid == 0) g_indptr[n] = wsum[31];
}

__global__ void k_fill(const int* __restrict__ src,
                       const int* __restrict__ dst, int E, int n) {
    int i = blockIdx.x * blockDim.x + threadIdx.x;
    if (i < E) {
        int d = dst[i];
        int s = src[i];
        d = max(0, min(n - 1, d));
        s = max(0, min(n - 1, s));
        int p = atomicAdd(&g_cursor[d], 1);
        if (p >= 0 && p < EDGES_MAX) {
            g_srcs[p] = s;
            g_wsrc[p] = g_dinv[s];
        }
    }
}

// ---------------- GEMM1: bf16 wmma, double-buffered, bf16 output ------------
#define B1_LDA 40
#define B1_LDB 136
#define B1_ASZ (128 * B1_LDA)
#define B1_BSZ (32 * B1_LDB)
#define B1_BUF (B1_ASZ + B1_BSZ)
#define B1_SMEM (2 * B1_BUF * 2)

__global__ void __launch_bounds__(256, 2) k_gemm1_wmma(const float* __restrict__ A,
                                                       const float* __restrict__ B,
                                                       int M, int N, int K) {
    const int BM = 128, BK = 32;
    extern __shared__ __align__(16) __nv_bfloat16 dynb[];

    const int tid = threadIdx.x;
    const int wid = tid >> 5;
    const int lid = tid & 31;
    const int warpRow = wid >> 2;      // 0..1 -> m*64
    const int warpCol = wid & 3;       // 0..3 -> n*32
    const int rowBase = blockIdx.y * BM;
    const int colBase = blockIdx.x * 128;

    const int a_r0 = tid >> 3;
    const int a_c  = (tid & 7) * 4;
    const int b_r0 = tid >> 5;
    const int b_c  = (tid & 31) * 4;

    wmma::fragment<wmma::accumulator, 16, 16, 16, float> acc[4][2];
    #pragma unroll
    for (int i = 0; i < 4; i++)
        #pragma unroll
        for (int j = 0; j < 2; j++)
            wmma::fill_fragment(acc[i][j], 0.0f);

    float4 a_pf[4], b_pf[4];

    #pragma unroll
    for (int h = 0; h < 4; h++) {
        int gr = rowBase + a_r0 + h * 32;
        a_pf[h] = make_float4(0.f, 0.f, 0.f, 0.f);
        if (gr < M) a_pf[h] = *reinterpret_cast<const float4*>(&A[(size_t)gr * K + a_c]);
        b_pf[h] = *reinterpret_cast<const float4*>(&B[(size_t)(b_r0 + h * 8) * N + colBase + b_c]);
    }
    {
        __nv_bfloat16* As = dynb;
        __nv_bfloat16* Bs = dynb + B1_ASZ;
        #pragma unroll
        for (int h = 0; h < 4; h++) {
            *reinterpret_cast<uint2*>(&As[(a_r0 + h * 32) * B1_LDA + a_c]) = f4_to_bf8(a_pf[h]);
            *reinterpret_cast<uint2*>(&Bs[(b_r0 + h * 8) * B1_LDB + b_c]) = f4_to_bf8(b_pf[h]);
        }
    }
    __syncthreads();

    const int nt = K / BK;   // 16
    for (int kt = 0; kt < nt; kt++) {
        const int cur = kt & 1;
        __nv_bfloat16* As = dynb + cur * B1_BUF;
        __nv_bfloat16* Bs = dynb + cur * B1_BUF + B1_ASZ;

        if (kt + 1 < nt) {
            int k0 = (kt + 1) * BK;
            #pragma unroll
            for (int h = 0; h < 4; h++) {
                int gr = rowBase + a_r0 + h * 32;
                a_pf[h] = make_float4(0.f, 0.f, 0.f, 0.f);
                if (gr < M)
                    a_pf[h] = *reinterpret_cast<const float4*>(&A[(size_t)gr * K + k0 + a_c]);
                b_pf[h] = *reinterpret_cast<const float4*>(&B[(size_t)(k0 + b_r0 + h * 8) * N + colBase + b_c]);
            }
        }

        #pragma unroll
        for (int k16 = 0; k16 < BK; k16 += 16) {
            wmma::fragment<wmma::matrix_a, 16, 16, 16, __nv_bfloat16, wmma::row_major> af[4];
            wmma::fragment<wmma::matrix_b, 16, 16, 16, __nv_bfloat16, wmma::row_major> bf[2];
            #pragma unroll
            for (int i = 0; i < 4; i++)
                wmma::load_matrix_sync(af[i], &As[(warpRow * 64 + i * 16) * B1_LDA + k16], B1_LDA);
            #pragma unroll
            for (int j = 0; j < 2; j++)
                wmma::load_matrix_sync(bf[j], &Bs[k16 * B1_LDB + warpCol * 32 + j * 16], B1_LDB);
            #pragma unroll
            for (int i = 0; i < 4; i++)
                #pragma unroll
                for (int j = 0; j < 2; j++)
                    wmma::mma_sync(acc[i][j], af[i], bf[j], acc[i][j]);
        }

        if (kt + 1 < nt) {
            __nv_bfloat16* Asn = dynb + (cur ^ 1) * B1_BUF;
            __nv_bfloat16* Bsn = dynb + (cur ^ 1) * B1_BUF + B1_ASZ;
            #pragma unroll
            for (int h = 0; h < 4; h++) {
                *reinterpret_cast<uint2*>(&Asn[(a_r0 + h * 32) * B1_LDA + a_c]) = f4_to_bf8(a_pf[h]);
                *reinterpret_cast<uint2*>(&Bsn[(b_r0 + h * 8) * B1_LDB + b_c]) = f4_to_bf8(b_pf[h]);
            }
        }
        __syncthreads();
    }

    // epilogue: per-atom smem roundtrip (reuse freed buffers), bf16 stores
    float* scratch = reinterpret_cast<float*>(dynb) + wid * 256;   // 1KB/warp
    #pragma unroll
    for (int i = 0; i < 4; i++) {
        #pragma unroll
        for (int j = 0; j < 2; j++) {
            wmma::store_matrix_sync(scratch, acc[i][j], 16, wmma::mem_row_major);
            __syncwarp();
            int r  = lid >> 1;
            int hh = (lid & 1) * 8;
            const float* p = scratch + r * 16 + hh;
            float4 lo = *reinterpret_cast<const float4*>(p);
            float4 hi = *reinterpret_cast<const float4*>(p + 4);
            uint2 u0 = f4_to_bf8(lo), u1 = f4_to_bf8(hi);
            uint4 o = make_uint4(u0.x, u0.y, u1.x, u1.y);
            int gr = rowBase + warpRow * 64 + i * 16 + r;       // < M_PAD
            int gc = colBase + warpCol * 32 + j * 16 + hh;
            *reinterpret_cast<uint4*>(&g_h1b[(size_t)gr * N + gc]) = o;
            __syncwarp();
        }
    }
}

// ---------------- GEMM2: bf16 wmma, A = g_agg1b (bf16), B = W2 (fp32) -------
#define B2_LDA 40
#define B2_LDB 72
#define B2_ASZ (128 * B2_LDA)
#define B2_BSZ (32 * B2_LDB)
#define B2_BUF (B2_ASZ + B2_BSZ)
#define B2_SMEM (2 * B2_BUF * 2)

__global__ void __launch_bounds__(256, 2) k_gemm2_wmma(const float* __restrict__ B,
                                                       int M) {
    const int BM = 128, BK = 32, K = HID, N = OUTC;
    extern __shared__ __align__(16) __nv_bfloat16 dynb[];

    const int tid = threadIdx.x;
    const int wid = tid >> 5;
    const int warpRow = wid >> 1;      // 0..3 -> m*32
    const int warpCol = wid & 1;       // 0..1 -> n*32
    const int rowBase = blockIdx.x * BM;

    // A loader: 8 bf16 (uint4) per access; 2 passes. row=tid>>2 (+64), c8=(tid&3)*8
    const int a_r0 = tid >> 2;
    const int a_c  = (tid & 3) * 8;
    // B loader: W2 fp32 -> bf16; 2 passes. row=tid>>4 (+16), c4=(tid&15)*4
    const int b_r0 = tid >> 4;
    const int b_c  = (tid & 15) * 4;

    wmma::fragment<wmma::accumulator, 16, 16, 16, float> acc[2][2];
    #pragma unroll
    for (int i = 0; i < 2; i++)
        #pragma unroll
        for (int j = 0; j < 2; j++)
            wmma::fill_fragment(acc[i][j], 0.0f);

    uint4  a_pf[2];
    float4 b_pf[2];

    #pragma unroll
    for (int h = 0; h < 2; h++) {
        int gr = rowBase + a_r0 + h * 64;
        a_pf[h] = make_uint4(0u, 0u, 0u, 0u);
        if (gr < M)
            a_pf[h] = *reinterpret_cast<const uint4*>(&g_agg1b[(size_t)gr * K + a_c]);
        b_pf[h] = *reinterpret_cast<const float4*>(&B[(size_t)(b_r0 + h * 16) * N + b_c]);
    }
    {
        __nv_bfloat16* As = dynb;
        __nv_bfloat16* Bs = dynb + B2_ASZ;
        #pragma unroll
        for (int h = 0; h < 2; h++) {
            *reinterpret_cast<uint4*>(&As[(a_r0 + h * 64) * B2_LDA + a_c]) = a_pf[h];
            *reinterpret_cast<uint2*>(&Bs[(b_r0 + h * 16) * B2_LDB + b_c]) = f4_to_bf8(b_pf[h]);
        }
    }
    __syncthreads();

    const int nt = K / BK;   // 8
    for (int kt = 0; kt < nt; kt++) {
        const int cur = kt & 1;
        __nv_bfloat16* As = dynb + cur * B2_BUF;
        __nv_bfloat16* Bs = dynb + cur * B2_BUF + B2_ASZ;

        if (kt + 1 < nt) {
            int k0 = (kt + 1) * BK;
            #pragma unroll
            for (int h = 0; h < 2; h++) {
                int gr = rowBase + a_r0 + h * 64;
                a_pf[h] = make_uint4(0u, 0u, 0u, 0u);
                if (gr < M)
                    a_pf[h] = *reinterpret_cast<const uint4*>(&g_agg1b[(size_t)gr * K + k0 + a_c]);
                b_pf[h] = *reinterpret_cast<const float4*>(&B[(size_t)(k0 + b_r0 + h * 16) * N + b_c]);
            }
        }

        #pragma unroll
        for (int k16 = 0; k16 < BK; k16 += 16) {
            wmma::fragment<wmma::matrix_a, 16, 16, 16, __nv_bfloat16, wmma::row_major> af[2];
            wmma::fragment<wmma::matrix_b, 16, 16, 16, __nv_bfloat16, wmma::row_major> bf[2];
            #pragma unroll
            for (int i = 0; i < 2; i++)
                wmma::load_matrix_sync(af[i], &As[(warpRow * 32 + i * 16) * B2_LDA + k16], B2_LDA);
            #pragma unroll
            for (int j = 0; j < 2; j++)
                wmma::load_matrix_sync(bf[j], &Bs[k16 * B2_LDB + warpCol * 32 + j * 16], B2_LDB);
            #pragma unroll
            for (int i = 0; i < 2; i++)
                #pragma unroll
                for (int j = 0; j < 2; j++)
                    wmma::mma_sync(acc[i][j], af[i], bf[j], acc[i][j]);
        }

        if (kt + 1 < nt) {
            __nv_bfloat16* Asn = dynb + (cur ^ 1) * B2_BUF;
            __nv_bfloat16* Bsn = dynb + (cur ^ 1) * B2_BUF + B2_ASZ;
            #pragma unroll
            for (int h = 0; h < 2; h++) {
                *reinterpret_cast<uint4*>(&Asn[(a_r0 + h * 64) * B2_LDA + a_c]) = a_pf[h];
                *reinterpret_cast<uint2*>(&Bsn[(b_r0 + h * 16) * B2_LDB + b_c]) = f4_to_bf8(b_pf[h]);
            }
        }
        __syncthreads();
    }

    // epilogue: fp32 direct (g_h2 rows padded to M_PAD)
    #pragma unroll
    for (int i = 0; i < 2; i++) {
        int r0 = rowBase + warpRow * 32 + i * 16;
        #pragma unroll
        for (int j = 0; j < 2; j++) {
            int c0 = warpCol * 32 + j * 16;
            wmma::store_matrix_sync(&g_h2[(size_t)r0 * N + c0], acc[i][j], N,
                                    wmma::mem_row_major);
        }
    }
}

// ---------------- layer-1 aggregation: bf16 gathers, fp32 accum -------------
__global__ void __launch_bounds__(256) k_agg1(const float* __restrict__ b1, int n) {
    int g = threadIdx.x >> 6;
    int l = threadIdx.x & 63;
    int d = blockIdx.x * 4 + g;
    if (d >= n) return;

    const uint2* h1v = reinterpret_cast<const uint2*>(g_h1b);
    float dd = g_dinv[d];
    float4 self = bf8_to_f4(h1v[(size_t)d * 64 + l]);
    float4 acc = make_float4(dd * self.x, dd * self.y, dd * self.z, dd * self.w);

    int beg = g_indptr[d], end = g_indptr[d + 1];
    #pragma unroll 8
    for (int t = beg; t < end; t++) {
        int s = g_srcs[t];
        float w = g_wsrc[t];
        float4 v = bf8_to_f4(h1v[(size_t)s * 64 + l]);
        acc.x = fmaf(w, v.x, acc.x);
        acc.y = fmaf(w, v.y, acc.y);
        acc.z = fmaf(w, v.z, acc.z);
        acc.w = fmaf(w, v.w, acc.w);
    }

    float4 b = reinterpret_cast<const float4*>(b1)[l];
    float4 o;
    o.x = fmaxf(fmaf(dd, acc.x, b.x), 0.0f);
    o.y = fmaxf(fmaf(dd, acc.y, b.y), 0.0f);
    o.z = fmaxf(fmaf(dd, acc.z, b.z), 0.0f);
    o.w = fmaxf(fmaf(dd, acc.w, b.w), 0.0f);
    reinterpret_cast<uint2*>(g_agg1b)[(size_t)d * 64 + l] = f4_to_bf8(o);
}

// ---------------- layer-2 agg + bias + log_softmax (barrier-free) -----------
__global__ void __launch_bounds__(256) k_agg2_lsm(const float* __restrict__ b2,
                                                  float* __restrict__ out, int n) {
    int g = threadIdx.x >> 4;
    int l = threadIdx.x & 15;
    int d = blockIdx.x * 16 + g;
    if (d >= n) return;

    const float4* h2v = reinterpret_cast<const float4*>(g_h2);
    float dd = g_dinv[d];
    float4 self = h2v[(size_t)d * 16 + l];
    float4 acc = make_float4(dd * self.x, dd * self.y, dd * self.z, dd * self.w);

    int beg = g_indptr[d], end = g_indptr[d + 1];
    #pragma unroll 8
    for (int t = beg; t < end; t++) {
        int s = g_srcs[t];
        float w = g_wsrc[t];
        float4 v = h2v[(size_t)s * 16 + l];
        acc.x = fmaf(w, v.x, acc.x);
        acc.y = fmaf(w, v.y, acc.y);
        acc.z = fmaf(w, v.z, acc.z);
        acc.w = fmaf(w, v.w, acc.w);
    }

    float4 b = reinterpret_cast<const float4*>(b2)[l];
    float4 v4;
    v4.x = fmaf(dd, acc.x, b.x);
    v4.y = fmaf(dd, acc.y, b.y);
    v4.z = fmaf(dd, acc.z, b.z);
    v4.w = fmaf(dd, acc.w, b.w);

    float m = fmaxf(fmaxf(v4.x, v4.y), fmaxf(v4.z, v4.w));
    #pragma unroll
    for (int o = 8; o; o >>= 1) m = fmaxf(m, __shfl_xor_sync(0xffffffffu, m, o));
    float s = expf(v4.x - m) + expf(v4.y - m) + expf(v4.z - m) + expf(v4.w - m);
    #pragma unroll
    for (int o = 8; o; o >>= 1) s += __shfl_xor_sync(0xffffffffu, s, o);
    float lse = m + logf(s);

    float4 o4;
    o4.x = v4.x - lse;  o4.y = v4.y - lse;
    o4.z = v4.z - lse;  o4.w = v4.w - lse;
    reinterpret_cast<float4*>(out)[(size_t)d * 16 + l] = o4;
}

// ---------------- entry -----------------------------------------------------
extern "C" void kernel_launch(void* const* d_in, const int* in_sizes, int n_in,
                              void* d_out, int out_size) {
    const float* x  = nullptr;
    const int*   ei = nullptr;
    const float* W1 = nullptr;
    const float* b1 = nullptr;
    const float* W2 = nullptr;
    const float* b2 = nullptr;

    for (int i = 0; i < n_in; i++) {
        long long s = in_sizes[i];
        if      (s == (long long)NODES_MAX * INC)   x  = (const float*)d_in[i];
        else if (s == 2LL * EDGES_MAX)              ei = (const int*)d_in[i];
        else if (s == (long long)INC * HID)         W1 = (const float*)d_in[i];
        else if (s == HID)                          b1 = (const float*)d_in[i];
        else if (s == (long long)HID * OUTC)        W2 = (const float*)d_in[i];
        else if (s == OUTC)                         b2 = (const float*)d_in[i];
    }
    if (!x  && n_in > 0) x  = (const float*)d_in[0];
    if (!ei && n_in > 1) ei = (const int*)d_in[1];
    if (!W1 && n_in > 2) W1 = (const float*)d_in[2];
    if (!b1 && n_in > 3) b1 = (const float*)d_in[3];
    if (!W2 && n_in > 4) W2 = (const float*)d_in[4];
    if (!b2 && n_in > 5) b2 = (const float*)d_in[5];

    float* out = (float*)d_out;

    int E  = EDGES_MAX;
    int Nn = out_size / OUTC;
    if (Nn > NODES_MAX) Nn = NODES_MAX;

    const int* src = ei;
    const int* dst = ei + E;

    int nb = (Nn + 255) / 256;
    int eb = (E + 255) / 256;

    // gemm1 stays at launch index 3 for the ncu capture window.
    k_zero_cnt<<<nb, 256>>>(Nn);
    k_count<<<eb, 256>>>(dst, E, Nn);
    k_scan2<<<1, 1024>>>(Nn);
    {
        dim3 grid(HID / 128, (Nn + 127) / 128);
        k_gemm1_wmma<<<grid, 256, B1_SMEM>>>(x, W1, Nn, HID, INC);   // index 3
    }
    k_fill<<<eb, 256>>>(src, dst, E, Nn);
    k_agg1<<<(Nn + 3) / 4, 256>>>(b1, Nn);
    k_gemm2_wmma<<<(Nn + 127) / 128, 256, B2_SMEM>>>(W2, Nn);
    k_agg2_lsm<<<(Nn + 15) / 16, 256>>>(b2, out, Nn);
}